// round 8
// baseline (speedup 1.0000x reference)
#include <cuda_runtime.h>
#include <math.h>

// Round 7: whole-CTA P1/P2/P3 (8 batches, Wq in regs), then TWO phase-shifted
// 256-thread teams (named barriers) each running P4..P8 on 4 batches.

#define NT 512
#define GRID 148

typedef unsigned long long ull;

#define OFF_WKT   0        // [128][65]  = 8320
#define OFF_WV    8320     // [64][128]  = 8192
#define OFF_WO    16512    // [128][64]  = 8192
#define OFF_BQ    24704    // 128
#define OFF_BV    24832    // 128
#define OFF_BO    24960    // 64
#define OFF_N     25024    // [8][20][68] = 10880
#define OFF_RAW   35904    // [192][8] = 1536
#define OFF_Q     37440    // [128][8] = 1024 (ull[c][4], 0.25 folded)
#define OFF_QK    38464    // [8][8][72] = 4608
#define OFF_SC    43072    // [8][8][28] = 1792
#define OFF_M     44864    // [8][8][72] = 4608
#define OFF_CTX   49472    // [8][128] = 1024
#define OFF_RED   50496    // 5120 (team tm uses [tm*2560, +2560))
#define OFF_V     55616    // [8][20] = 160
#define SMEM_FLOATS 55776
#define SMEM_BYTES  (SMEM_FLOATS * 4)

__device__ __forceinline__ ull pk1(float a) {
    ull r; asm("mov.b64 %0, {%1,%1};" : "=l"(r) : "f"(a)); return r;
}
__device__ __forceinline__ void fma2(ull& d, ull a, ull b) {
    asm("fma.rn.f32x2 %0, %1, %2, %0;" : "+l"(d) : "l"(a), "l"(b));
}
__device__ __forceinline__ ull add2(ull a, ull b) {
    ull r; asm("add.rn.f32x2 %0, %1, %2;" : "=l"(r) : "l"(a), "l"(b)); return r;
}
__device__ __forceinline__ ull mul2(ull a, ull b) {
    ull r; asm("mul.rn.f32x2 %0, %1, %2;" : "=l"(r) : "l"(a), "l"(b)); return r;
}
__device__ __forceinline__ float2 upk(ull a) {
    float2 f; asm("mov.b64 {%0,%1}, %2;" : "=f"(f.x), "=f"(f.y) : "l"(a)); return f;
}
#define TEAM_BAR(tm) asm volatile("bar.sync %0, %1;" :: "r"((tm) + 1), "r"(256) : "memory")

__global__ void __launch_bounds__(NT, 1)
mha_state_encoder_kernel(const float* __restrict__ node_embed,
                         const int*   __restrict__ start_idx,
                         const int*   __restrict__ end_idx,
                         const int*   __restrict__ pad_idx,
                         const float* __restrict__ Wq, const float* __restrict__ bq,
                         const float* __restrict__ Wk,
                         const float* __restrict__ Wv, const float* __restrict__ bv,
                         const float* __restrict__ Wo, const float* __restrict__ bo,
                         float* __restrict__ out, int B)
{
    extern __shared__ float sm[];
    float* sWKT = sm + OFF_WKT;
    float* sWV  = sm + OFF_WV;
    float* sWO  = sm + OFF_WO;
    float* sBQ  = sm + OFF_BQ;
    float* sBV  = sm + OFF_BV;
    float* sBO  = sm + OFF_BO;
    float* sN   = sm + OFF_N;
    float* sRAW = sm + OFF_RAW;
    float* sQ   = sm + OFF_Q;
    float* sQK  = sm + OFF_QK;
    float* sSC  = sm + OFF_SC;
    float* sM   = sm + OFF_M;
    float* sCTX = sm + OFF_CTX;
    float* sRED = sm + OFF_RED;
    float* sV   = sm + OFF_V;
    ull*   sRED2 = reinterpret_cast<ull*>(sRED);
    ull*   sQ2   = reinterpret_cast<ull*>(sQ);

    const int t  = threadIdx.x;
    const int tm = t >> 8;          // team 0/1
    const int u  = t & 255;         // lane within team
    const int Q  = B >> 3;

    // ---- stage weights ----
    for (int i = t; i < 8192; i += NT) {
        int d = i >> 7, c = i & 127;
        sWKT[c * 65 + d] = Wk[i];
    }
    for (int i = t; i < 2048; i += NT) {
        reinterpret_cast<float4*>(sWV)[i] = reinterpret_cast<const float4*>(Wv)[i];
        reinterpret_cast<float4*>(sWO)[i] = reinterpret_cast<const float4*>(Wo)[i];
    }
    if (t < 128) { sBQ[t] = bq[t]; sBV[t] = bv[t]; }
    if (t < 64)  sBO[t] = bo[t];

    // Wq register slice (whole-CTA P3)
    const int c127 = t & 127;
    const int rg   = t >> 7;
    float wq[48];
    {
        const float* src = Wq + (size_t)(rg * 48) * 128 + c127;
        #pragma unroll
        for (int i = 0; i < 48; ++i) wq[i] = src[(size_t)i * 128];
    }

    // gather thread geometry (t in [256,512)), gnb fastest
    const int gidx = t - 256;
    const int gnb  = gidx & 7;
    const int gwh  = (gidx >> 3) & 1;
    const int gdq  = gidx >> 4;

    float4 pfN[5];
    float4 pfG = make_float4(0.f, 0.f, 0.f, 0.f);
    int    pfP = 0, gi_next = 0;

    int q0 = blockIdx.x;
    if (q0 < Q) {
        int b0 = q0 * 8;
        const float4* nsrc = reinterpret_cast<const float4*>(node_embed) + (size_t)b0 * 320;
        #pragma unroll
        for (int k = 0; k < 5; ++k) pfN[k] = nsrc[t + k * 512];
        if (t < 160) pfP = pad_idx[b0 * 20 + t];
        if (t >= 256) {
            int gi = gwh ? end_idx[b0 + gnb] : start_idx[b0 + gnb];
            pfG = *reinterpret_cast<const float4*>(node_embed + (size_t)gi * 64 + gdq * 4);
            int qn = q0 + GRID;
            if (qn < Q) gi_next = gwh ? end_idx[qn * 8 + gnb] : start_idx[qn * 8 + gnb];
        }
    }
    __syncthreads();

    for (int q = q0; q < Q; q += GRID) {
        const int b0 = q * 8;

        // ===== P1: commit prefetched data (whole CTA) =====
        {
            float4* sN4 = reinterpret_cast<float4*>(sN);
            #pragma unroll
            for (int k = 0; k < 5; ++k) {
                int g   = t + k * 512;
                int nb  = g / 320;
                int rem = g - nb * 320;
                sN4[nb * 340 + (rem >> 4) * 17 + (rem & 15)] = pfN[k];
            }
            if (t < 160) sV[t] = (pfP >= 0) ? 1.0f : 0.0f;
            if (t >= 256) {
                int r0 = 64 + gwh * 64 + gdq * 4;
                sRAW[(r0 + 0) * 8 + gnb] = pfG.x;
                sRAW[(r0 + 1) * 8 + gnb] = pfG.y;
                sRAW[(r0 + 2) * 8 + gnb] = pfG.z;
                sRAW[(r0 + 3) * 8 + gnb] = pfG.w;
            }
        }
        {
            int qn = q + GRID;
            if (qn < Q) {
                int bn = qn * 8;
                const float4* nsrc = reinterpret_cast<const float4*>(node_embed) + (size_t)bn * 320;
                #pragma unroll
                for (int k = 0; k < 5; ++k) pfN[k] = nsrc[t + k * 512];
                if (t < 160) pfP = pad_idx[bn * 20 + t];
                if (t >= 256) {
                    pfG = *reinterpret_cast<const float4*>(node_embed + (size_t)gi_next * 64 + gdq * 4);
                    int qn2 = qn + GRID;
                    if (qn2 < Q) gi_next = gwh ? end_idx[qn2 * 8 + gnb] : start_idx[qn2 * 8 + gnb];
                }
            }
        }
        __syncthreads();

        // ===== P2: agg (whole CTA, 128 active) =====
        if (t < 128) {
            int nb = t >> 4, dq = t & 15;
            const float4* col = reinterpret_cast<const float4*>(sN + nb * 1360) + dq;
            float ax = 0.f, ay = 0.f, az = 0.f, aw = 0.f;
            #pragma unroll
            for (int j = 0; j < 20; ++j) {
                float4 x = col[j * 17];
                ax += x.x; ay += x.y; az += x.z; aw += x.w;
            }
            int r0 = dq * 4;
            sRAW[(r0 + 0) * 8 + nb] = ax;
            sRAW[(r0 + 1) * 8 + nb] = ay;
            sRAW[(r0 + 2) * 8 + nb] = az;
            sRAW[(r0 + 3) * 8 + nb] = aw;
        }
        __syncthreads();

        // ===== P3: q = raw @ Wq (whole CTA, f32x2) =====
        {
            const ulonglong2* pR = reinterpret_cast<const ulonglong2*>(sRAW) + rg * 96;
            ull a01 = 0, a23 = 0, a45 = 0, a67 = 0;
            #pragma unroll
            for (int i = 0; i < 48; ++i) {
                ulonglong2 x = pR[2 * i];
                ulonglong2 y = pR[2 * i + 1];
                ull wp = pk1(wq[i]);
                fma2(a01, wp, x.x);
                fma2(a23, wp, x.y);
                fma2(a45, wp, y.x);
                fma2(a67, wp, y.y);
            }
            ull* dst = sRED2 + rg * 640 + c127 * 5;
            dst[0] = a01; dst[1] = a23; dst[2] = a45; dst[3] = a67;
        }
        __syncthreads();
        {
            int c = t >> 2, pp = t & 3;
            ull v = add2(add2(sRED2[c * 5 + pp], sRED2[640 + c * 5 + pp]),
                         add2(sRED2[1280 + c * 5 + pp], sRED2[1920 + c * 5 + pp]));
            v = add2(v, pk1(sBQ[c]));
            v = mul2(v, pk1(0.25f));
            sQ2[t] = v;
        }
        __syncthreads();

        // ============ TEAM REGION: team tm handles batches tm*4 .. tm*4+3 ======
        const int nb0 = tm * 4;
        float* tRED = sRED + tm * 2560;

        // ===== P4 (team): qk[nb0..+3][h][d], f32x2, 2 passes =====
        #pragma unroll
        for (int p = 0; p < 2; ++p) {
            int v2 = u + p * 256;
            int h = v2 >> 6, d = v2 & 63;
            const float* wkb = sWKT + h * 16 * 65 + d;
            ull a01 = 0, a23 = 0;
            #pragma unroll
            for (int i = 0; i < 16; ++i) {
                ull wp = pk1(wkb[i * 65]);
                ulonglong2 qv = *reinterpret_cast<const ulonglong2*>(sQ2 + (h * 16 + i) * 4 + tm * 2);
                fma2(a01, wp, qv.x);
                fma2(a23, wp, qv.y);
            }
            float2 f01 = upk(a01), f23 = upk(a23);
            float* dst = sQK + h * 72 + d;
            dst[(nb0 + 0) * 576] = f01.x; dst[(nb0 + 1) * 576] = f01.y;
            dst[(nb0 + 2) * 576] = f23.x; dst[(nb0 + 3) * 576] = f23.y;
        }
        TEAM_BAR(tm);

        // ===== P5 (team): scores + inline mask; 160 active =====
        if (u < 160) {
            int nbl = u / 40;
            int r   = u - nbl * 40;
            int j   = r >> 1;
            int hh  = r & 1;
            int nb  = nb0 + nbl;
            const float4* n4  = reinterpret_cast<const float4*>(sN + nb * 1360 + j * 68);
            const float*  qkb = sQK + nb * 576 + (hh * 4) * 72;
            float s0 = 0.f, s1 = 0.f, s2 = 0.f, s3 = 0.f, rsum = 0.f;
            #pragma unroll
            for (int k = 0; k < 16; ++k) {
                float4 x  = n4[k];
                rsum += (x.x + x.y) + (x.z + x.w);
                float4 a0 = *reinterpret_cast<const float4*>(qkb + 0 * 72 + k * 4);
                float4 a1 = *reinterpret_cast<const float4*>(qkb + 1 * 72 + k * 4);
                float4 a2 = *reinterpret_cast<const float4*>(qkb + 2 * 72 + k * 4);
                float4 a3 = *reinterpret_cast<const float4*>(qkb + 3 * 72 + k * 4);
                s0 = fmaf(a0.x,x.x,s0); s0 = fmaf(a0.y,x.y,s0); s0 = fmaf(a0.z,x.z,s0); s0 = fmaf(a0.w,x.w,s0);
                s1 = fmaf(a1.x,x.x,s1); s1 = fmaf(a1.y,x.y,s1); s1 = fmaf(a1.z,x.z,s1); s1 = fmaf(a1.w,x.w,s1);
                s2 = fmaf(a2.x,x.x,s2); s2 = fmaf(a2.y,x.y,s2); s2 = fmaf(a2.z,x.z,s2); s2 = fmaf(a2.w,x.w,s2);
                s3 = fmaf(a3.x,x.x,s3); s3 = fmaf(a3.y,x.y,s3); s3 = fmaf(a3.z,x.z,s3); s3 = fmaf(a3.w,x.w,s3);
            }
            float msk = (sV[nb * 20 + j] == 0.f || rsum == 0.f) ? -1e9f : 0.f;
            float* dst = sSC + nb * 224 + (hh * 4) * 28 + j;
            dst[0 * 28] = s0 + msk;
            dst[1 * 28] = s1 + msk;
            dst[2 * 28] = s2 + msk;
            dst[3 * 28] = s3 + msk;
        }
        TEAM_BAR(tm);

        // ===== softmax (team): 32 rows x 4 lanes, shfl reduce =====
        if (u < 128) {
            int row = u >> 2, j0 = u & 3;
            int nbl = row >> 3, h = row & 7;
            int nb  = nb0 + nbl;
            float* base = sSC + nb * 224 + h * 28;
            const float* vd = sV + nb * 20;
            float x0 = base[j0], x1 = base[j0+4], x2 = base[j0+8], x3 = base[j0+12], x4 = base[j0+16];
            float mx = fmaxf(fmaxf(fmaxf(x0, x1), fmaxf(x2, x3)), x4);
            mx = fmaxf(mx, __shfl_xor_sync(0xffffffffu, mx, 1));
            mx = fmaxf(mx, __shfl_xor_sync(0xffffffffu, mx, 2));
            float e0 = __expf(x0 - mx), e1 = __expf(x1 - mx), e2 = __expf(x2 - mx);
            float e3 = __expf(x3 - mx), e4 = __expf(x4 - mx);
            float s = ((e0 + e1) + (e2 + e3)) + e4;
            s += __shfl_xor_sync(0xffffffffu, s, 1);
            s += __shfl_xor_sync(0xffffffffu, s, 2);
            float inv = __fdividef(1.f, s);
            base[j0]      = e0 * inv * vd[j0];
            base[j0 + 4]  = e1 * inv * vd[j0 + 4];
            base[j0 + 8]  = e2 * inv * vd[j0 + 8];
            base[j0 + 12] = e3 * inv * vd[j0 + 12];
            base[j0 + 16] = e4 * inv * vd[j0 + 16];
        }
        TEAM_BAR(tm);

        // ===== P6 (team): m — 2 heads/thread, all 256 active =====
        {
            int nbl = u >> 6, dq = (u >> 2) & 15, hg = u & 3;   // heads hg*2, hg*2+1
            int nb  = nb0 + nbl;
            const float4* n4 = reinterpret_cast<const float4*>(sN + nb * 1360) + dq;
            const float* a0 = sSC + nb * 224 + (hg * 2 + 0) * 28;
            const float* a1 = sSC + nb * 224 + (hg * 2 + 1) * 28;
            float4 m0 = make_float4(0,0,0,0), m1 = make_float4(0,0,0,0);
            #pragma unroll
            for (int jq = 0; jq < 5; ++jq) {
                float4 w0 = *reinterpret_cast<const float4*>(a0 + jq * 4);
                float4 w1 = *reinterpret_cast<const float4*>(a1 + jq * 4);
                #pragma unroll
                for (int jj = 0; jj < 4; ++jj) {
                    float4 x = n4[(jq * 4 + jj) * 17];
                    float c0 = jj == 0 ? w0.x : jj == 1 ? w0.y : jj == 2 ? w0.z : w0.w;
                    float c1 = jj == 0 ? w1.x : jj == 1 ? w1.y : jj == 2 ? w1.z : w1.w;
                    m0.x = fmaf(c0,x.x,m0.x); m0.y = fmaf(c0,x.y,m0.y); m0.z = fmaf(c0,x.z,m0.z); m0.w = fmaf(c0,x.w,m0.w);
                    m1.x = fmaf(c1,x.x,m1.x); m1.y = fmaf(c1,x.y,m1.y); m1.z = fmaf(c1,x.z,m1.z); m1.w = fmaf(c1,x.w,m1.w);
                }
            }
            float* mb = sM + nb * 576 + (hg * 2) * 72 + dq * 4;
            *reinterpret_cast<float4*>(mb + 0 * 72) = m0;
            *reinterpret_cast<float4*>(mb + 1 * 72) = m1;
        }
        TEAM_BAR(tm);

        // ===== P7 (team): ctx partials (2-way d split) =====
        {
            int cc = u & 127, dh = u >> 7, d0 = dh * 32, h = cc >> 4;
            float acc[4] = {0,0,0,0};
            #pragma unroll
            for (int kq = 0; kq < 8; ++kq) {
                int d = d0 + kq * 4;
                float w0 = sWV[(d+0)*128 + cc], w1 = sWV[(d+1)*128 + cc];
                float w2 = sWV[(d+2)*128 + cc], w3 = sWV[(d+3)*128 + cc];
                #pragma unroll
                for (int nbl = 0; nbl < 4; ++nbl) {
                    float4 m = *reinterpret_cast<const float4*>(sM + (nb0+nbl)*576 + h*72 + d);
                    acc[nbl] = fmaf(w0, m.x, fmaf(w1, m.y, fmaf(w2, m.z, fmaf(w3, m.w, acc[nbl]))));
                }
            }
            #pragma unroll
            for (int nbl = 0; nbl < 4; ++nbl)
                tRED[dh * 512 + nbl * 128 + cc] = acc[nbl];
        }
        TEAM_BAR(tm);
        #pragma unroll
        for (int p = 0; p < 2; ++p) {
            int e   = u + p * 256;
            int nbl = e >> 7, cc = e & 127;
            sCTX[(nb0+nbl) * 128 + cc] = tRED[nbl*128+cc] + tRED[512 + nbl*128+cc] + sBV[cc];
        }
        TEAM_BAR(tm);

        // ===== P8 (team): out partials (4-way c split) =====
        {
            int o = u & 63, cg = u >> 6, c0 = cg * 32;
            float acc[4] = {0,0,0,0};
            #pragma unroll
            for (int kq = 0; kq < 8; ++kq) {
                int c = c0 + kq * 4;
                float w0 = sWO[(c+0)*64 + o], w1 = sWO[(c+1)*64 + o];
                float w2 = sWO[(c+2)*64 + o], w3 = sWO[(c+3)*64 + o];
                #pragma unroll
                for (int nbl = 0; nbl < 4; ++nbl) {
                    float4 x = *reinterpret_cast<const float4*>(sCTX + (nb0+nbl)*128 + c);
                    acc[nbl] = fmaf(w0, x.x, fmaf(w1, x.y, fmaf(w2, x.z, fmaf(w3, x.w, acc[nbl]))));
                }
            }
            #pragma unroll
            for (int nbl = 0; nbl < 4; ++nbl)
                tRED[cg * 256 + nbl * 64 + o] = acc[nbl];
        }
        TEAM_BAR(tm);
        {
            int nbl = u >> 6, o = u & 63;
            float s = ((tRED[0*256 + nbl*64 + o] + tRED[1*256 + nbl*64 + o]) +
                       (tRED[2*256 + nbl*64 + o] + tRED[3*256 + nbl*64 + o])) + sBO[o];
            out[(size_t)(b0 + nb0 + nbl) * 64 + o] = s;
        }
        __syncthreads();   // iteration end: both teams done before P1 overwrites
    }
}

extern "C" void kernel_launch(void* const* d_in, const int* in_sizes, int n_in,
                              void* d_out, int out_size)
{
    const float* node_embed = (const float*)d_in[0];
    const int*   start_idx  = (const int*)d_in[1];
    const int*   end_idx    = (const int*)d_in[2];
    /* d_in[3] seg_ids unused (structural) */
    const int*   pad_idx    = (const int*)d_in[4];
    const float* Wq         = (const float*)d_in[5];
    const float* bq         = (const float*)d_in[6];
    const float* Wk         = (const float*)d_in[7];
    /* d_in[8] bk unused (cancels in softmax) */
    const float* Wv         = (const float*)d_in[9];
    const float* bv         = (const float*)d_in[10];
    const float* Wo         = (const float*)d_in[11];
    const float* bo         = (const float*)d_in[12];
    float* out = (float*)d_out;

    int B = out_size / 64;

    cudaFuncSetAttribute(mha_state_encoder_kernel,
                         cudaFuncAttributeMaxDynamicSharedMemorySize, SMEM_BYTES);
    mha_state_encoder_kernel<<<GRID, NT, SMEM_BYTES>>>(
        node_embed, start_idx, end_idx, pad_idx,
        Wq, bq, Wk, Wv, bv, Wo, bo, out, B);
}

// round 9
// speedup vs baseline: 1.0536x; 1.0536x over previous
#include <cuda_runtime.h>
#include <math.h>

// Round 8: whole-CTA (R6 base) + P3 2-column register blocking (broadcast
// stream halved; 8 partial slices staged in dead QK/SC/M region) + 256-thread
// quad-shfl softmax.

#define NT 512
#define GRID 148

typedef unsigned long long ull;

#define OFF_WKT   0        // [128][65]  = 8320
#define OFF_WV    8320     // [64][128]  = 8192
#define OFF_WO    16512    // [128][64]  = 8192
#define OFF_BQ    24704    // 128
#define OFF_BV    24832    // 128
#define OFF_BO    24960    // 64
#define OFF_N     25024    // [8][20][68] = 10880
#define OFF_RAW   35904    // [192][8] = 1536
#define OFF_Q     37440    // [128][8] = 1024 (ull[c][4], 0.25 folded)
#define OFF_QK    38464    // [8][8][72] = 4608   } QK+SC+M region doubles as
#define OFF_SC    43072    // [8][8][28] = 1792   } P3 partial scratch
#define OFF_M     44864    // [8][8][72] = 4608   } (8192 floats needed, 11008 avail)
#define OFF_CTX   49472    // [8][128] = 1024
#define OFF_RED   50496    // 5120 floats (P7/P8 partials)
#define OFF_V     55616    // [8][20] = 160
#define SMEM_FLOATS 55776
#define SMEM_BYTES  (SMEM_FLOATS * 4)

__device__ __forceinline__ ull pk1(float a) {
    ull r; asm("mov.b64 %0, {%1,%1};" : "=l"(r) : "f"(a)); return r;
}
__device__ __forceinline__ void fma2(ull& d, ull a, ull b) {
    asm("fma.rn.f32x2 %0, %1, %2, %0;" : "+l"(d) : "l"(a), "l"(b));
}
__device__ __forceinline__ ull add2(ull a, ull b) {
    ull r; asm("add.rn.f32x2 %0, %1, %2;" : "=l"(r) : "l"(a), "l"(b)); return r;
}
__device__ __forceinline__ ull mul2(ull a, ull b) {
    ull r; asm("mul.rn.f32x2 %0, %1, %2;" : "=l"(r) : "l"(a), "l"(b)); return r;
}
__device__ __forceinline__ float2 upk(ull a) {
    float2 f; asm("mov.b64 {%0,%1}, %2;" : "=f"(f.x), "=f"(f.y) : "l"(a)); return f;
}

__global__ void __launch_bounds__(NT, 1)
mha_state_encoder_kernel(const float* __restrict__ node_embed,
                         const int*   __restrict__ start_idx,
                         const int*   __restrict__ end_idx,
                         const int*   __restrict__ pad_idx,
                         const float* __restrict__ Wq, const float* __restrict__ bq,
                         const float* __restrict__ Wk,
                         const float* __restrict__ Wv, const float* __restrict__ bv,
                         const float* __restrict__ Wo, const float* __restrict__ bo,
                         float* __restrict__ out, int B)
{
    extern __shared__ float sm[];
    float* sWKT = sm + OFF_WKT;
    float* sWV  = sm + OFF_WV;
    float* sWO  = sm + OFF_WO;
    float* sBQ  = sm + OFF_BQ;
    float* sBV  = sm + OFF_BV;
    float* sBO  = sm + OFF_BO;
    float* sN   = sm + OFF_N;
    float* sRAW = sm + OFF_RAW;
    float* sQ   = sm + OFF_Q;
    float* sQK  = sm + OFF_QK;
    float* sSC  = sm + OFF_SC;
    float* sM   = sm + OFF_M;
    float* sCTX = sm + OFF_CTX;
    float* sRED = sm + OFF_RED;
    float* sV   = sm + OFF_V;
    ull*   sQ2   = reinterpret_cast<ull*>(sQ);
    ull*   pPART = reinterpret_cast<ull*>(sm + OFF_QK);  // P3 partials: [8][128][4] ull

    const int t = threadIdx.x;
    const int Q = B >> 3;

    // ---- stage weights ----
    for (int i = t; i < 8192; i += NT) {
        int d = i >> 7, c = i & 127;
        sWKT[c * 65 + d] = Wk[i];
    }
    for (int i = t; i < 2048; i += NT) {
        reinterpret_cast<float4*>(sWV)[i] = reinterpret_cast<const float4*>(Wv)[i];
        reinterpret_cast<float4*>(sWO)[i] = reinterpret_cast<const float4*>(Wo)[i];
    }
    if (t < 128) { sBQ[t] = bq[t]; sBV[t] = bv[t]; }
    if (t < 64)  sBO[t] = bo[t];

    // Wq register slice: cols {cl, cl+64}, rows rg8*24 .. +23
    const int cl  = t & 63;
    const int rg8 = t >> 6;           // 0..7
    float wq[48];
    {
        const float* src = Wq + (size_t)(rg8 * 24) * 128 + cl;
        #pragma unroll
        for (int i = 0; i < 24; ++i) {
            wq[2 * i + 0] = src[(size_t)i * 128];
            wq[2 * i + 1] = src[(size_t)i * 128 + 64];
        }
    }

    // gather thread geometry (t in [256,512)), gnb fastest
    const int gidx = t - 256;
    const int gnb  = gidx & 7;
    const int gwh  = (gidx >> 3) & 1;
    const int gdq  = gidx >> 4;

    float4 pfN[5];
    float4 pfG = make_float4(0.f, 0.f, 0.f, 0.f);
    int    pfP = 0, gi_next = 0;

    int q0 = blockIdx.x;
    if (q0 < Q) {
        int b0 = q0 * 8;
        const float4* nsrc = reinterpret_cast<const float4*>(node_embed) + (size_t)b0 * 320;
        #pragma unroll
        for (int k = 0; k < 5; ++k) pfN[k] = nsrc[t + k * 512];
        if (t < 160) pfP = pad_idx[b0 * 20 + t];
        if (t >= 256) {
            int gi = gwh ? end_idx[b0 + gnb] : start_idx[b0 + gnb];
            pfG = *reinterpret_cast<const float4*>(node_embed + (size_t)gi * 64 + gdq * 4);
            int qn = q0 + GRID;
            if (qn < Q) gi_next = gwh ? end_idx[qn * 8 + gnb] : start_idx[qn * 8 + gnb];
        }
    }
    __syncthreads();

    for (int q = q0; q < Q; q += GRID) {
        const int b0 = q * 8;

        // ===== P1: commit prefetched data =====
        {
            float4* sN4 = reinterpret_cast<float4*>(sN);
            #pragma unroll
            for (int k = 0; k < 5; ++k) {
                int g   = t + k * 512;
                int nb  = g / 320;
                int rem = g - nb * 320;
                sN4[nb * 340 + (rem >> 4) * 17 + (rem & 15)] = pfN[k];
            }
            if (t < 160) sV[t] = (pfP >= 0) ? 1.0f : 0.0f;
            if (t >= 256) {
                int r0 = 64 + gwh * 64 + gdq * 4;
                sRAW[(r0 + 0) * 8 + gnb] = pfG.x;
                sRAW[(r0 + 1) * 8 + gnb] = pfG.y;
                sRAW[(r0 + 2) * 8 + gnb] = pfG.z;
                sRAW[(r0 + 3) * 8 + gnb] = pfG.w;
            }
        }
        // issue next-group prefetch
        {
            int qn = q + GRID;
            if (qn < Q) {
                int bn = qn * 8;
                const float4* nsrc = reinterpret_cast<const float4*>(node_embed) + (size_t)bn * 320;
                #pragma unroll
                for (int k = 0; k < 5; ++k) pfN[k] = nsrc[t + k * 512];
                if (t < 160) pfP = pad_idx[bn * 20 + t];
                if (t >= 256) {
                    pfG = *reinterpret_cast<const float4*>(node_embed + (size_t)gi_next * 64 + gdq * 4);
                    int qn2 = qn + GRID;
                    if (qn2 < Q) gi_next = gwh ? end_idx[qn2 * 8 + gnb] : start_idx[qn2 * 8 + gnb];
                }
            }
        }
        __syncthreads();

        // ===== P2: agg =====
        if (t < 128) {
            int nb = t >> 4, dq = t & 15;
            const float4* col = reinterpret_cast<const float4*>(sN + nb * 1360) + dq;
            float ax = 0.f, ay = 0.f, az = 0.f, aw = 0.f;
            #pragma unroll
            for (int j = 0; j < 20; ++j) {
                float4 x = col[j * 17];
                ax += x.x; ay += x.y; az += x.z; aw += x.w;
            }
            int r0 = dq * 4;
            sRAW[(r0 + 0) * 8 + nb] = ax;
            sRAW[(r0 + 1) * 8 + nb] = ay;
            sRAW[(r0 + 2) * 8 + nb] = az;
            sRAW[(r0 + 3) * 8 + nb] = aw;
        }
        __syncthreads();

        // ===== P3: q = raw @ Wq — 2-col blocking, f32x2, 8 row-slices =====
        {
            const ulonglong2* pR = reinterpret_cast<const ulonglong2*>(sRAW) + rg8 * 48;
            ull a01 = 0, a23 = 0, a45 = 0, a67 = 0;   // col cl
            ull b01 = 0, b23 = 0, b45 = 0, b67 = 0;   // col cl+64
            #pragma unroll
            for (int i = 0; i < 24; ++i) {
                ulonglong2 x = pR[2 * i];
                ulonglong2 y = pR[2 * i + 1];
                ull w0 = pk1(wq[2 * i + 0]);
                ull w1 = pk1(wq[2 * i + 1]);
                fma2(a01, w0, x.x); fma2(a23, w0, x.y);
                fma2(a45, w0, y.x); fma2(a67, w0, y.y);
                fma2(b01, w1, x.x); fma2(b23, w1, x.y);
                fma2(b45, w1, y.x); fma2(b67, w1, y.y);
            }
            ull* dA = pPART + rg8 * 512 + cl * 4;
            dA[0] = a01; dA[1] = a23; dA[2] = a45; dA[3] = a67;
            ull* dB = pPART + rg8 * 512 + (cl + 64) * 4;
            dB[0] = b01; dB[1] = b23; dB[2] = b45; dB[3] = b67;
        }
        __syncthreads();
        {   // combine 8 slices + bias + fold 0.25
            int c = t >> 2, pp = t & 3;
            int o = c * 4 + pp;
            ull v = add2(add2(pPART[o],           pPART[512 + o]),
                         add2(pPART[1024 + o],    pPART[1536 + o]));
            ull w = add2(add2(pPART[2048 + o],    pPART[2560 + o]),
                         add2(pPART[3072 + o],    pPART[3584 + o]));
            v = add2(add2(v, w), pk1(sBQ[c]));
            v = mul2(v, pk1(0.25f));
            sQ2[t] = v;
        }
        __syncthreads();

        // ===== P4: qk[nb][h][d] (f32x2, whole CTA) =====
        {
            int h = t >> 6, d = t & 63;
            const float* wkb = sWKT + h * 16 * 65 + d;
            const ulonglong2* q2 = reinterpret_cast<const ulonglong2*>(sQ) + h * 16 * 2;
            ull a01 = 0, a23 = 0, a45 = 0, a67 = 0;
            #pragma unroll
            for (int i = 0; i < 16; ++i) {
                ull wp = pk1(wkb[i * 65]);
                ulonglong2 x = q2[2 * i];
                ulonglong2 y = q2[2 * i + 1];
                fma2(a01, wp, x.x);
                fma2(a23, wp, x.y);
                fma2(a45, wp, y.x);
                fma2(a67, wp, y.y);
            }
            float2 f01 = upk(a01), f23 = upk(a23), f45 = upk(a45), f67 = upk(a67);
            float* dst = sQK + h * 72 + d;
            dst[0 * 576] = f01.x; dst[1 * 576] = f01.y;
            dst[2 * 576] = f23.x; dst[3 * 576] = f23.y;
            dst[4 * 576] = f45.x; dst[5 * 576] = f45.y;
            dst[6 * 576] = f67.x; dst[7 * 576] = f67.y;
        }
        __syncthreads();

        // ===== P5: scores + inline mask =====
        if (t < 320) {
            int nb = t / 40;
            int r  = t - nb * 40;
            int j  = r >> 1;
            int hh = r & 1;
            const float4* n4  = reinterpret_cast<const float4*>(sN + nb * 1360 + j * 68);
            const float*  qkb = sQK + nb * 576 + (hh * 4) * 72;
            float s0 = 0.f, s1 = 0.f, s2 = 0.f, s3 = 0.f, rsum = 0.f;
            #pragma unroll
            for (int k = 0; k < 16; ++k) {
                float4 x  = n4[k];
                rsum += (x.x + x.y) + (x.z + x.w);
                float4 a0 = *reinterpret_cast<const float4*>(qkb + 0 * 72 + k * 4);
                float4 a1 = *reinterpret_cast<const float4*>(qkb + 1 * 72 + k * 4);
                float4 a2 = *reinterpret_cast<const float4*>(qkb + 2 * 72 + k * 4);
                float4 a3 = *reinterpret_cast<const float4*>(qkb + 3 * 72 + k * 4);
                s0 = fmaf(a0.x,x.x,s0); s0 = fmaf(a0.y,x.y,s0); s0 = fmaf(a0.z,x.z,s0); s0 = fmaf(a0.w,x.w,s0);
                s1 = fmaf(a1.x,x.x,s1); s1 = fmaf(a1.y,x.y,s1); s1 = fmaf(a1.z,x.z,s1); s1 = fmaf(a1.w,x.w,s1);
                s2 = fmaf(a2.x,x.x,s2); s2 = fmaf(a2.y,x.y,s2); s2 = fmaf(a2.z,x.z,s2); s2 = fmaf(a2.w,x.w,s2);
                s3 = fmaf(a3.x,x.x,s3); s3 = fmaf(a3.y,x.y,s3); s3 = fmaf(a3.z,x.z,s3); s3 = fmaf(a3.w,x.w,s3);
            }
            float msk = (sV[nb * 20 + j] == 0.f || rsum == 0.f) ? -1e9f : 0.f;
            float* dst = sSC + nb * 224 + (hh * 4) * 28 + j;
            dst[0 * 28] = s0 + msk;
            dst[1 * 28] = s1 + msk;
            dst[2 * 28] = s2 + msk;
            dst[3 * 28] = s3 + msk;
        }
        __syncthreads();

        // ===== softmax: 64 rows x 4 lanes, quad-shfl reduce =====
        if (t < 256) {
            int row = t >> 2, j0 = t & 3;
            int nb = row >> 3, h = row & 7;
            float* base = sSC + nb * 224 + h * 28;
            const float* vd = sV + nb * 20;
            float x0 = base[j0], x1 = base[j0+4], x2 = base[j0+8], x3 = base[j0+12], x4 = base[j0+16];
            float mx = fmaxf(fmaxf(fmaxf(x0, x1), fmaxf(x2, x3)), x4);
            mx = fmaxf(mx, __shfl_xor_sync(0xffffffffu, mx, 1));
            mx = fmaxf(mx, __shfl_xor_sync(0xffffffffu, mx, 2));
            float e0 = __expf(x0 - mx), e1 = __expf(x1 - mx), e2 = __expf(x2 - mx);
            float e3 = __expf(x3 - mx), e4 = __expf(x4 - mx);
            float s = ((e0 + e1) + (e2 + e3)) + e4;
            s += __shfl_xor_sync(0xffffffffu, s, 1);
            s += __shfl_xor_sync(0xffffffffu, s, 2);
            float inv = __fdividef(1.f, s);
            base[j0]      = e0 * inv * vd[j0];
            base[j0 + 4]  = e1 * inv * vd[j0 + 4];
            base[j0 + 8]  = e2 * inv * vd[j0 + 8];
            base[j0 + 12] = e3 * inv * vd[j0 + 12];
            base[j0 + 16] = e4 * inv * vd[j0 + 16];
        }
        __syncthreads();

        // ===== P6: m — 4 heads/thread (node tile read once) =====
        if (t < 256) {
            int nb = t >> 5, dq = (t >> 1) & 15, hg = t & 1;
            const float4* n4 = reinterpret_cast<const float4*>(sN + nb * 1360) + dq;
            const float* a0 = sSC + nb * 224 + (hg * 4 + 0) * 28;
            const float* a1 = sSC + nb * 224 + (hg * 4 + 1) * 28;
            const float* a2 = sSC + nb * 224 + (hg * 4 + 2) * 28;
            const float* a3 = sSC + nb * 224 + (hg * 4 + 3) * 28;
            float4 m0 = make_float4(0,0,0,0), m1 = make_float4(0,0,0,0);
            float4 m2 = make_float4(0,0,0,0), m3 = make_float4(0,0,0,0);
            #pragma unroll
            for (int jq = 0; jq < 5; ++jq) {
                float4 w0 = *reinterpret_cast<const float4*>(a0 + jq * 4);
                float4 w1 = *reinterpret_cast<const float4*>(a1 + jq * 4);
                float4 w2 = *reinterpret_cast<const float4*>(a2 + jq * 4);
                float4 w3 = *reinterpret_cast<const float4*>(a3 + jq * 4);
                #pragma unroll
                for (int jj = 0; jj < 4; ++jj) {
                    float4 x = n4[(jq * 4 + jj) * 17];
                    float c0 = jj == 0 ? w0.x : jj == 1 ? w0.y : jj == 2 ? w0.z : w0.w;
                    float c1 = jj == 0 ? w1.x : jj == 1 ? w1.y : jj == 2 ? w1.z : w1.w;
                    float c2 = jj == 0 ? w2.x : jj == 1 ? w2.y : jj == 2 ? w2.z : w2.w;
                    float c3 = jj == 0 ? w3.x : jj == 1 ? w3.y : jj == 2 ? w3.z : w3.w;
                    m0.x = fmaf(c0,x.x,m0.x); m0.y = fmaf(c0,x.y,m0.y); m0.z = fmaf(c0,x.z,m0.z); m0.w = fmaf(c0,x.w,m0.w);
                    m1.x = fmaf(c1,x.x,m1.x); m1.y = fmaf(c1,x.y,m1.y); m1.z = fmaf(c1,x.z,m1.z); m1.w = fmaf(c1,x.w,m1.w);
                    m2.x = fmaf(c2,x.x,m2.x); m2.y = fmaf(c2,x.y,m2.y); m2.z = fmaf(c2,x.z,m2.z); m2.w = fmaf(c2,x.w,m2.w);
                    m3.x = fmaf(c3,x.x,m3.x); m3.y = fmaf(c3,x.y,m3.y); m3.z = fmaf(c3,x.z,m3.z); m3.w = fmaf(c3,x.w,m3.w);
                }
            }
            float* mb = sM + nb * 576 + (hg * 4) * 72 + dq * 4;
            *reinterpret_cast<float4*>(mb + 0 * 72) = m0;
            *reinterpret_cast<float4*>(mb + 1 * 72) = m1;
            *reinterpret_cast<float4*>(mb + 2 * 72) = m2;
            *reinterpret_cast<float4*>(mb + 3 * 72) = m3;
        }
        __syncthreads();

        // ===== P7: ctx partials (whole CTA, 4-way d split) =====
        {
            int cc = t & 127, dh = t >> 7, d0 = dh * 16, h = cc >> 4;
            float acc[8] = {0,0,0,0,0,0,0,0};
            #pragma unroll
            for (int kq = 0; kq < 4; ++kq) {
                int d = d0 + kq * 4;
                float w0 = sWV[(d+0)*128 + cc], w1 = sWV[(d+1)*128 + cc];
                float w2 = sWV[(d+2)*128 + cc], w3 = sWV[(d+3)*128 + cc];
                #pragma unroll
                for (int nb = 0; nb < 8; ++nb) {
                    float4 m = *reinterpret_cast<const float4*>(sM + nb*576 + h*72 + d);
                    acc[nb] = fmaf(w0, m.x, fmaf(w1, m.y, fmaf(w2, m.z, fmaf(w3, m.w, acc[nb]))));
                }
            }
            #pragma unroll
            for (int nb = 0; nb < 8; ++nb)
                sRED[dh * 1024 + nb * 128 + cc] = acc[nb];
        }
        __syncthreads();
        #pragma unroll
        for (int p = 0; p < 2; ++p) {
            int e  = t + p * 512;
            int nb = e >> 7, cc = e & 127;
            sCTX[nb * 128 + cc] = ((sRED[nb*128+cc] + sRED[1024 + nb*128+cc]) +
                                   (sRED[2048 + nb*128+cc] + sRED[3072 + nb*128+cc])) + sBV[cc];
        }
        __syncthreads();

        // ===== P8: out partials (whole CTA, 8-way c split) =====
        {
            int o = t & 63, cg = t >> 6, c0 = cg * 16;
            float acc[8] = {0,0,0,0,0,0,0,0};
            #pragma unroll
            for (int kq = 0; kq < 4; ++kq) {
                int c = c0 + kq * 4;
                float w0 = sWO[(c+0)*64 + o], w1 = sWO[(c+1)*64 + o];
                float w2 = sWO[(c+2)*64 + o], w3 = sWO[(c+3)*64 + o];
                #pragma unroll
                for (int nb = 0; nb < 8; ++nb) {
                    float4 x = *reinterpret_cast<const float4*>(sCTX + nb*128 + c);
                    acc[nb] = fmaf(w0, x.x, fmaf(w1, x.y, fmaf(w2, x.z, fmaf(w3, x.w, acc[nb]))));
                }
            }
            #pragma unroll
            for (int nb = 0; nb < 8; ++nb)
                sRED[cg * 512 + nb * 64 + o] = acc[nb];
        }
        __syncthreads();
        {
            int nb = t >> 6, o = t & 63;
            float s = 0.f;
            #pragma unroll
            for (int cg = 0; cg < 8; ++cg) s += sRED[cg * 512 + nb * 64 + o];
            out[(size_t)(b0 + nb) * 64 + o] = s + sBO[o];
        }
    }
}

extern "C" void kernel_launch(void* const* d_in, const int* in_sizes, int n_in,
                              void* d_out, int out_size)
{
    const float* node_embed = (const float*)d_in[0];
    const int*   start_idx  = (const int*)d_in[1];
    const int*   end_idx    = (const int*)d_in[2];
    /* d_in[3] seg_ids unused (structural) */
    const int*   pad_idx    = (const int*)d_in[4];
    const float* Wq         = (const float*)d_in[5];
    const float* bq         = (const float*)d_in[6];
    const float* Wk         = (const float*)d_in[7];
    /* d_in[8] bk unused (cancels in softmax) */
    const float* Wv         = (const float*)d_in[9];
    const float* bv         = (const float*)d_in[10];
    const float* Wo         = (const float*)d_in[11];
    const float* bo         = (const float*)d_in[12];
    float* out = (float*)d_out;

    int B = out_size / 64;

    cudaFuncSetAttribute(mha_state_encoder_kernel,
                         cudaFuncAttributeMaxDynamicSharedMemorySize, SMEM_BYTES);
    mha_state_encoder_kernel<<<GRID, NT, SMEM_BYTES>>>(
        node_embed, start_idx, end_idx, pad_idx,
        Wq, bq, Wk, Wv, bv, Wo, bo, out, B);
}

// round 11
// speedup vs baseline: 1.0902x; 1.0348x over previous
#include <cuda_runtime.h>
#include <cstdint>
#include <math.h>

// Round 10: warp-specialized producer/consumer pipeline (R9 + cstdint fix).
// Producer (threads 0..255): cp.async node tiles (triple-buffered), gathers,
//   agg, P3 (Wq in regs, f32x2), P4 (qk) -> double-buffered sQK.
// Consumer (threads 256..383): P5 scores+mask, softmax, P6 weighted sums,
//   P7 ctx, P8 out — one group behind the producer.

#define NT 384
#define GRID 148

typedef unsigned long long ull;

// shared memory float offsets
#define OFF_WKT   0        // [128][65]
#define OFF_WV    8320     // [64][128]
#define OFF_WO    16512    // [128][64]
#define OFF_BQ    24704
#define OFF_BV    24832
#define OFF_BO    24960
#define OFF_N     25024    // [3][4][20][68] = 16320 (triple-buffered node tiles)
#define OFF_V     41344    // [3][4][20] = 240
#define OFF_QK    41584    // [2][4][8][72] = 4608 (double-buffered qk)
#define OFF_RAW   46192    // [192][4] = 768 (producer-private)
#define OFF_Q     46960    // [128][4] = 512 (producer-private)
#define OFF_PART  47472    // [4][128][3] ull = 3072 floats (producer-private)
#define OFF_SC    50544    // [4][8][28] = 896 (consumer-private)
#define OFF_M     51440    // [4][8][72] = 2304 (consumer-private)
#define OFF_CTX   53744    // [4][128] = 512 (consumer-private)
#define OFF_RED8  54256    // [2][4][64] = 512 (consumer-private)
#define SMEM_FLOATS 54768
#define SMEM_BYTES  (SMEM_FLOATS * 4)   // 219072 B

// named barrier ids
#define BFULL0 1   // +qb : producer(arrive 256) -> consumer(sync 128), total 384
#define BEQ0   3   // +qb : consumer(arrive) -> producer(sync)
#define BEN0   5   // +nb3: consumer(arrive) -> producer(sync)
#define BPROD  8   // producer-internal, 256
#define BCONS  9   // consumer-internal, 128

#define BAR_SYNC(id, cnt)   asm volatile("bar.sync %0, %1;"   :: "r"(id), "r"(cnt) : "memory")
#define BAR_ARRIVE(id, cnt) asm volatile("bar.arrive %0, %1;" :: "r"(id), "r"(cnt) : "memory")
#define CP_COMMIT()         asm volatile("cp.async.commit_group;" ::: "memory")
#define CP_WAIT1()          asm volatile("cp.async.wait_group 1;" ::: "memory")

__device__ __forceinline__ ull pk1(float a) {
    ull r; asm("mov.b64 %0, {%1,%1};" : "=l"(r) : "f"(a)); return r;
}
__device__ __forceinline__ void fma2(ull& d, ull a, ull b) {
    asm("fma.rn.f32x2 %0, %1, %2, %0;" : "+l"(d) : "l"(a), "l"(b));
}
__device__ __forceinline__ ull add2(ull a, ull b) {
    ull r; asm("add.rn.f32x2 %0, %1, %2;" : "=l"(r) : "l"(a), "l"(b)); return r;
}
__device__ __forceinline__ ull mul2(ull a, ull b) {
    ull r; asm("mul.rn.f32x2 %0, %1, %2;" : "=l"(r) : "l"(a), "l"(b)); return r;
}
__device__ __forceinline__ float2 upk(ull a) {
    float2 f; asm("mov.b64 {%0,%1}, %2;" : "=f"(f.x), "=f"(f.y) : "l"(a)); return f;
}

// issue 5x 16B cp.async for one group's node tile into buffer nbuf
__device__ __forceinline__ void issue_node_cp(unsigned int sbase, const float* ne,
                                              int b0, int nbuf, int t) {
    const float4* src = reinterpret_cast<const float4*>(ne) + (size_t)b0 * 320;
    #pragma unroll
    for (int kk = 0; kk < 5; ++kk) {
        int g   = t + kk * 256;
        int nb  = g / 320;
        int rem = g - nb * 320;
        unsigned int dstf = (unsigned int)(OFF_N + nbuf * 5440 + nb * 1360 +
                                           ((rem >> 4) * 17 + (rem & 15)) * 4);
        asm volatile("cp.async.ca.shared.global [%0], [%1], 16;"
                     :: "r"(sbase + dstf * 4), "l"(src + g) : "memory");
    }
}

__global__ void __launch_bounds__(NT, 1)
mha_state_encoder_kernel(const float* __restrict__ node_embed,
                         const int*   __restrict__ start_idx,
                         const int*   __restrict__ end_idx,
                         const int*   __restrict__ pad_idx,
                         const float* __restrict__ Wq, const float* __restrict__ bq,
                         const float* __restrict__ Wk,
                         const float* __restrict__ Wv, const float* __restrict__ bv,
                         const float* __restrict__ Wo, const float* __restrict__ bo,
                         float* __restrict__ out, int B)
{
    extern __shared__ float sm[];
    float* sWKT = sm + OFF_WKT;
    float* sWV  = sm + OFF_WV;
    float* sWO  = sm + OFF_WO;
    float* sBQ  = sm + OFF_BQ;
    float* sBV  = sm + OFF_BV;
    float* sBO  = sm + OFF_BO;
    float* sN   = sm + OFF_N;
    float* sV   = sm + OFF_V;
    float* sQK  = sm + OFF_QK;
    float* sRAW = sm + OFF_RAW;
    float* sSC  = sm + OFF_SC;
    float* sM   = sm + OFF_M;
    float* sCTX = sm + OFF_CTX;
    float* sRED8= sm + OFF_RED8;
    ull*   sQ2  = reinterpret_cast<ull*>(sm + OFF_Q);
    ull*   sPT  = reinterpret_cast<ull*>(sm + OFF_PART);

    unsigned int sbase;
    asm("{ .reg .u64 tt; cvta.to.shared.u64 tt, %1; cvt.u32.u64 %0, tt; }"
        : "=r"(sbase) : "l"(sm));

    const int t  = threadIdx.x;
    const int Qn = B >> 2;            // 4-batch groups
    const int q0 = blockIdx.x;

    // ---- stage weights (whole CTA) ----
    for (int i = t; i < 8192; i += NT) {
        int d = i >> 7, c = i & 127;
        sWKT[c * 65 + d] = Wk[i];
    }
    for (int i = t; i < 2048; i += NT) {
        reinterpret_cast<float4*>(sWV)[i] = reinterpret_cast<const float4*>(Wv)[i];
        reinterpret_cast<float4*>(sWO)[i] = reinterpret_cast<const float4*>(Wo)[i];
    }
    if (t < 128) { sBQ[t] = bq[t]; sBV[t] = bv[t]; }
    if (t < 64)  sBO[t] = bo[t];
    __syncthreads();   // ONLY whole-CTA sync; everything below is divergent teams

    if (t < 256) {
        // ======================= PRODUCER (256 threads) =======================
        const int cl = t & 63;
        const int rg = t >> 6;            // 0..3 row slices (48 rows each)
        float wq[96];                     // 48 rows x cols {cl, cl+64}
        {
            const float* src = Wq + (size_t)(rg * 48) * 128 + cl;
            #pragma unroll
            for (int i = 0; i < 24; ++i) {
                wq[4*i+0] = src[(size_t)(2*i)   * 128];
                wq[4*i+1] = src[(size_t)(2*i)   * 128 + 64];
                wq[4*i+2] = src[(size_t)(2*i+1) * 128];
                wq[4*i+3] = src[(size_t)(2*i+1) * 128 + 64];
            }
        }
        // gather geometry (threads 128..255): 4 nb x 2 wh x 16 dq = 128
        const int gg  = t - 128;
        const int gnb = gg & 3;
        const int gwh = (gg >> 2) & 1;
        const int gdq = gg >> 3;

        float4 pfG = make_float4(0.f, 0.f, 0.f, 0.f);
        int pfP = 0, gi_next = 0;

        // pre-loop: node cp.async for groups q0, q0+GRID; gather prefetch for q0
        if (q0 < Qn)        issue_node_cp(sbase, node_embed, q0 * 4, 0, t);
        CP_COMMIT();
        if (q0 + GRID < Qn) issue_node_cp(sbase, node_embed, (q0 + GRID) * 4, 1, t);
        CP_COMMIT();
        if (q0 < Qn) {
            if (t >= 128) {
                int gi = gwh ? end_idx[q0 * 4 + gnb] : start_idx[q0 * 4 + gnb];
                pfG = *reinterpret_cast<const float4*>(node_embed + (size_t)gi * 64 + gdq * 4);
                int qn = q0 + GRID;
                if (qn < Qn) gi_next = gwh ? end_idx[qn * 4 + gnb] : start_idx[qn * 4 + gnb];
            }
            if (t < 80) pfP = pad_idx[q0 * 80 + t];
        }

        int it = 0, nb3 = 0;
        for (int q = q0; q < Qn; q += GRID, ++it) {
            const int qb = it & 1;

            CP_WAIT1();   // this group's node tile landed

            // commit gathers + valid flags
            if (t >= 128) {
                int r0 = 64 + gwh * 64 + gdq * 4;
                sRAW[(r0 + 0) * 4 + gnb] = pfG.x;
                sRAW[(r0 + 1) * 4 + gnb] = pfG.y;
                sRAW[(r0 + 2) * 4 + gnb] = pfG.z;
                sRAW[(r0 + 3) * 4 + gnb] = pfG.w;
            }
            if (t < 80) sV[nb3 * 80 + t] = (pfP >= 0) ? 1.0f : 0.0f;
            // prefetch gathers for next group
            if (q + GRID < Qn) {
                if (t >= 128) {
                    pfG = *reinterpret_cast<const float4*>(node_embed + (size_t)gi_next * 64 + gdq * 4);
                    int qn2 = q + 2 * GRID;
                    if (qn2 < Qn) gi_next = gwh ? end_idx[qn2 * 4 + gnb] : start_idx[qn2 * 4 + gnb];
                }
                if (t < 80) pfP = pad_idx[(q + GRID) * 80 + t];
            }
            BAR_SYNC(BPROD, 256);

            // ---- P2: agg (column sums) ----
            if (t < 64) {
                int nb = t >> 4, dq = t & 15;
                const float4* col = reinterpret_cast<const float4*>(sN + nb3 * 5440 + nb * 1360) + dq;
                float ax = 0.f, ay = 0.f, az = 0.f, aw = 0.f;
                #pragma unroll
                for (int j = 0; j < 20; ++j) {
                    float4 x = col[j * 17];
                    ax += x.x; ay += x.y; az += x.z; aw += x.w;
                }
                int r0 = dq * 4;
                sRAW[(r0 + 0) * 4 + nb] = ax;
                sRAW[(r0 + 1) * 4 + nb] = ay;
                sRAW[(r0 + 2) * 4 + nb] = az;
                sRAW[(r0 + 3) * 4 + nb] = aw;
            }
            BAR_SYNC(BPROD, 256);

            // ---- P3a: q partials (f32x2, 4 row slices x 2 cols) ----
            {
                const ulonglong2* pR = reinterpret_cast<const ulonglong2*>(sRAW) + rg * 48;
                ull a0 = 0, a1 = 0, b0u = 0, b1u = 0;
                #pragma unroll
                for (int i = 0; i < 24; ++i) {
                    ulonglong2 x = pR[2 * i];
                    ulonglong2 y = pR[2 * i + 1];
                    ull w0 = pk1(wq[4*i+0]), w1 = pk1(wq[4*i+1]);
                    ull w2 = pk1(wq[4*i+2]), w3 = pk1(wq[4*i+3]);
                    fma2(a0,  w0, x.x); fma2(a1,  w0, x.y);
                    fma2(b0u, w1, x.x); fma2(b1u, w1, x.y);
                    fma2(a0,  w2, y.x); fma2(a1,  w2, y.y);
                    fma2(b0u, w3, y.x); fma2(b1u, w3, y.y);
                }
                ull* dA = sPT + rg * 384 + cl * 3;
                dA[0] = a0; dA[1] = a1;
                ull* dB = sPT + rg * 384 + (cl + 64) * 3;
                dB[0] = b0u; dB[1] = b1u;
            }
            BAR_SYNC(BPROD, 256);

            // ---- P3b: combine slices + bias + 0.25 scale -> sQ ----
            {
                int c = t >> 1, pp = t & 1;
                int o = c * 3 + pp;
                ull v = add2(add2(sPT[o], sPT[384 + o]),
                             add2(sPT[768 + o], sPT[1152 + o]));
                v = add2(v, pk1(sBQ[c]));
                v = mul2(v, pk1(0.25f));
                sQ2[c * 2 + pp] = v;
            }
            BAR_SYNC(BPROD, 256);

            // ---- P4: qk -> sQK[qb] ----
            if (it >= 2) BAR_SYNC(BEQ0 + qb, 384);
            #pragma unroll
            for (int p = 0; p < 2; ++p) {
                int v2 = t + p * 256;
                int h = v2 >> 6, d = v2 & 63;
                const float* wkb = sWKT + h * 16 * 65 + d;
                const ulonglong2* q2 = reinterpret_cast<const ulonglong2*>(sQ2) + h * 16;
                ull a01 = 0, a23 = 0;
                #pragma unroll
                for (int i = 0; i < 16; ++i) {
                    ull wp = pk1(wkb[i * 65]);
                    ulonglong2 qv = q2[i];
                    fma2(a01, wp, qv.x);
                    fma2(a23, wp, qv.y);
                }
                float2 f01 = upk(a01), f23 = upk(a23);
                float* dst = sQK + qb * 2304 + h * 72 + d;
                dst[0 * 576] = f01.x; dst[1 * 576] = f01.y;
                dst[2 * 576] = f23.x; dst[3 * 576] = f23.y;
            }
            BAR_ARRIVE(BFULL0 + qb, 384);

            // ---- issue node cp.async for group q+2*GRID ----
            {
                int nb3p2 = nb3 + 2; if (nb3p2 >= 3) nb3p2 -= 3;
                if (q + 2 * GRID < Qn) {
                    if (it >= 1) BAR_SYNC(BEN0 + nb3p2, 384);
                    issue_node_cp(sbase, node_embed, (q + 2 * GRID) * 4, nb3p2, t);
                }
                CP_COMMIT();   // possibly empty group: keeps wait_group bookkeeping uniform
            }
            if (++nb3 == 3) nb3 = 0;
        }
    } else {
        // ======================= CONSUMER (128 threads) =======================
        const int u = t - 256;
        int it = 0, nb3 = 0;
        for (int q = q0; q < Qn; q += GRID, ++it) {
            const int b0 = q * 4;
            const int qb = it & 1;
            const float* nbase = sN + nb3 * 5440;
            const float* vbase = sV + nb3 * 80;
            const float* qkB   = sQK + qb * 2304;

            BAR_SYNC(BFULL0 + qb, 384);   // qk + nodes + valid ready

            // ---- P5: scores + inline mask (160 tasks) ----
            for (int v = u; v < 160; v += 128) {
                int nb = v / 40;
                int r  = v - nb * 40;
                int j  = r >> 1;
                int hh = r & 1;
                const float4* n4  = reinterpret_cast<const float4*>(nbase + nb * 1360 + j * 68);
                const float*  qkb = qkB + nb * 576 + (hh * 4) * 72;
                float s0 = 0.f, s1 = 0.f, s2 = 0.f, s3 = 0.f, rsum = 0.f;
                #pragma unroll
                for (int k = 0; k < 16; ++k) {
                    float4 x  = n4[k];
                    rsum += (x.x + x.y) + (x.z + x.w);
                    float4 a0 = *reinterpret_cast<const float4*>(qkb + 0 * 72 + k * 4);
                    float4 a1 = *reinterpret_cast<const float4*>(qkb + 1 * 72 + k * 4);
                    float4 a2 = *reinterpret_cast<const float4*>(qkb + 2 * 72 + k * 4);
                    float4 a3 = *reinterpret_cast<const float4*>(qkb + 3 * 72 + k * 4);
                    s0 = fmaf(a0.x,x.x,s0); s0 = fmaf(a0.y,x.y,s0); s0 = fmaf(a0.z,x.z,s0); s0 = fmaf(a0.w,x.w,s0);
                    s1 = fmaf(a1.x,x.x,s1); s1 = fmaf(a1.y,x.y,s1); s1 = fmaf(a1.z,x.z,s1); s1 = fmaf(a1.w,x.w,s1);
                    s2 = fmaf(a2.x,x.x,s2); s2 = fmaf(a2.y,x.y,s2); s2 = fmaf(a2.z,x.z,s2); s2 = fmaf(a2.w,x.w,s2);
                    s3 = fmaf(a3.x,x.x,s3); s3 = fmaf(a3.y,x.y,s3); s3 = fmaf(a3.z,x.z,s3); s3 = fmaf(a3.w,x.w,s3);
                }
                float msk = (vbase[nb * 20 + j] == 0.f || rsum == 0.f) ? -1e9f : 0.f;
                float* dst = sSC + nb * 224 + (hh * 4) * 28 + j;
                dst[0 * 28] = s0 + msk;
                dst[1 * 28] = s1 + msk;
                dst[2 * 28] = s2 + msk;
                dst[3 * 28] = s3 + msk;
            }
            BAR_SYNC(BCONS, 128);
            BAR_ARRIVE(BEQ0 + qb, 384);    // done with sQK[qb]

            // ---- softmax: 32 rows x 4 lanes ----
            {
                int row = u >> 2, j0 = u & 3;
                int nb = row >> 3, h = row & 7;
                float* base = sSC + nb * 224 + h * 28;
                const float* vd = vbase + nb * 20;
                float x0 = base[j0], x1 = base[j0+4], x2 = base[j0+8], x3 = base[j0+12], x4 = base[j0+16];
                float mx = fmaxf(fmaxf(fmaxf(x0, x1), fmaxf(x2, x3)), x4);
                mx = fmaxf(mx, __shfl_xor_sync(0xffffffffu, mx, 1));
                mx = fmaxf(mx, __shfl_xor_sync(0xffffffffu, mx, 2));
                float e0 = __expf(x0 - mx), e1 = __expf(x1 - mx), e2 = __expf(x2 - mx);
                float e3 = __expf(x3 - mx), e4 = __expf(x4 - mx);
                float s = ((e0 + e1) + (e2 + e3)) + e4;
                s += __shfl_xor_sync(0xffffffffu, s, 1);
                s += __shfl_xor_sync(0xffffffffu, s, 2);
                float inv = __fdividef(1.f, s);
                base[j0]      = e0 * inv * vd[j0];
                base[j0 + 4]  = e1 * inv * vd[j0 + 4];
                base[j0 + 8]  = e2 * inv * vd[j0 + 8];
                base[j0 + 12] = e3 * inv * vd[j0 + 12];
                base[j0 + 16] = e4 * inv * vd[j0 + 16];
            }
            BAR_SYNC(BCONS, 128);

            // ---- P6: m (4 heads/thread, 128 tasks) ----
            {
                int nb = u >> 5, dq = (u >> 1) & 15, hg = u & 1;
                const float4* n4 = reinterpret_cast<const float4*>(nbase + nb * 1360) + dq;
                const float* a0 = sSC + nb * 224 + (hg * 4 + 0) * 28;
                const float* a1 = sSC + nb * 224 + (hg * 4 + 1) * 28;
                const float* a2 = sSC + nb * 224 + (hg * 4 + 2) * 28;
                const float* a3 = sSC + nb * 224 + (hg * 4 + 3) * 28;
                float4 m0 = make_float4(0,0,0,0), m1 = make_float4(0,0,0,0);
                float4 m2 = make_float4(0,0,0,0), m3 = make_float4(0,0,0,0);
                #pragma unroll
                for (int jq = 0; jq < 5; ++jq) {
                    float4 w0 = *reinterpret_cast<const float4*>(a0 + jq * 4);
                    float4 w1 = *reinterpret_cast<const float4*>(a1 + jq * 4);
                    float4 w2 = *reinterpret_cast<const float4*>(a2 + jq * 4);
                    float4 w3 = *reinterpret_cast<const float4*>(a3 + jq * 4);
                    #pragma unroll
                    for (int jj = 0; jj < 4; ++jj) {
                        float4 x = n4[(jq * 4 + jj) * 17];
                        float c0 = jj == 0 ? w0.x : jj == 1 ? w0.y : jj == 2 ? w0.z : w0.w;
                        float c1 = jj == 0 ? w1.x : jj == 1 ? w1.y : jj == 2 ? w1.z : w1.w;
                        float c2 = jj == 0 ? w2.x : jj == 1 ? w2.y : jj == 2 ? w2.z : w2.w;
                        float c3 = jj == 0 ? w3.x : jj == 1 ? w3.y : jj == 2 ? w3.z : w3.w;
                        m0.x = fmaf(c0,x.x,m0.x); m0.y = fmaf(c0,x.y,m0.y); m0.z = fmaf(c0,x.z,m0.z); m0.w = fmaf(c0,x.w,m0.w);
                        m1.x = fmaf(c1,x.x,m1.x); m1.y = fmaf(c1,x.y,m1.y); m1.z = fmaf(c1,x.z,m1.z); m1.w = fmaf(c1,x.w,m1.w);
                        m2.x = fmaf(c2,x.x,m2.x); m2.y = fmaf(c2,x.y,m2.y); m2.z = fmaf(c2,x.z,m2.z); m2.w = fmaf(c2,x.w,m2.w);
                        m3.x = fmaf(c3,x.x,m3.x); m3.y = fmaf(c3,x.y,m3.y); m3.z = fmaf(c3,x.z,m3.z); m3.w = fmaf(c3,x.w,m3.w);
                    }
                }
                float* mb = sM + nb * 576 + (hg * 4) * 72 + dq * 4;
                *reinterpret_cast<float4*>(mb + 0 * 72) = m0;
                *reinterpret_cast<float4*>(mb + 1 * 72) = m1;
                *reinterpret_cast<float4*>(mb + 2 * 72) = m2;
                *reinterpret_cast<float4*>(mb + 3 * 72) = m3;
            }
            BAR_SYNC(BCONS, 128);
            BAR_ARRIVE(BEN0 + nb3, 384);   // done with sN/sV buffer

            // ---- P7: ctx (full 64-d dot, no partials) ----
            {
                int cc = u, h = u >> 4;
                float acc0 = 0.f, acc1 = 0.f, acc2 = 0.f, acc3 = 0.f;
                #pragma unroll
                for (int kq = 0; kq < 16; ++kq) {
                    int d = kq * 4;
                    float w0 = sWV[(d+0)*128 + cc], w1 = sWV[(d+1)*128 + cc];
                    float w2 = sWV[(d+2)*128 + cc], w3 = sWV[(d+3)*128 + cc];
                    float4 m0 = *reinterpret_cast<const float4*>(sM + 0*576 + h*72 + d);
                    float4 m1 = *reinterpret_cast<const float4*>(sM + 1*576 + h*72 + d);
                    float4 m2 = *reinterpret_cast<const float4*>(sM + 2*576 + h*72 + d);
                    float4 m3 = *reinterpret_cast<const float4*>(sM + 3*576 + h*72 + d);
                    acc0 = fmaf(w0,m0.x,fmaf(w1,m0.y,fmaf(w2,m0.z,fmaf(w3,m0.w,acc0))));
                    acc1 = fmaf(w0,m1.x,fmaf(w1,m1.y,fmaf(w2,m1.z,fmaf(w3,m1.w,acc1))));
                    acc2 = fmaf(w0,m2.x,fmaf(w1,m2.y,fmaf(w2,m2.z,fmaf(w3,m2.w,acc2))));
                    acc3 = fmaf(w0,m3.x,fmaf(w1,m3.y,fmaf(w2,m3.z,fmaf(w3,m3.w,acc3))));
                }
                float bvv = sBV[cc];
                sCTX[0 * 128 + cc] = acc0 + bvv;
                sCTX[1 * 128 + cc] = acc1 + bvv;
                sCTX[2 * 128 + cc] = acc2 + bvv;
                sCTX[3 * 128 + cc] = acc3 + bvv;
            }
            BAR_SYNC(BCONS, 128);

            // ---- P8: out partials (2-way c split) ----
            {
                int o = u & 63, cg = u >> 6, c0 = cg * 64;
                float acc0 = 0.f, acc1 = 0.f, acc2 = 0.f, acc3 = 0.f;
                #pragma unroll
                for (int kq = 0; kq < 16; ++kq) {
                    int c = c0 + kq * 4;
                    float w0 = sWO[(c+0)*64 + o], w1 = sWO[(c+1)*64 + o];
                    float w2 = sWO[(c+2)*64 + o], w3 = sWO[(c+3)*64 + o];
                    float4 x0 = *reinterpret_cast<const float4*>(sCTX + 0*128 + c);
                    float4 x1 = *reinterpret_cast<const float4*>(sCTX + 1*128 + c);
                    float4 x2 = *reinterpret_cast<const float4*>(sCTX + 2*128 + c);
                    float4 x3 = *reinterpret_cast<const float4*>(sCTX + 3*128 + c);
                    acc0 = fmaf(w0,x0.x,fmaf(w1,x0.y,fmaf(w2,x0.z,fmaf(w3,x0.w,acc0))));
                    acc1 = fmaf(w0,x1.x,fmaf(w1,x1.y,fmaf(w2,x1.z,fmaf(w3,x1.w,acc1))));
                    acc2 = fmaf(w0,x2.x,fmaf(w1,x2.y,fmaf(w2,x2.z,fmaf(w3,x2.w,acc2))));
                    acc3 = fmaf(w0,x3.x,fmaf(w1,x3.y,fmaf(w2,x3.z,fmaf(w3,x3.w,acc3))));
                }
                sRED8[cg * 256 + 0 * 64 + o] = acc0;
                sRED8[cg * 256 + 1 * 64 + o] = acc1;
                sRED8[cg * 256 + 2 * 64 + o] = acc2;
                sRED8[cg * 256 + 3 * 64 + o] = acc3;
            }
            BAR_SYNC(BCONS, 128);
            #pragma unroll
            for (int p = 0; p < 2; ++p) {
                int e  = u + p * 128;
                int nb = e >> 6, o = e & 63;
                out[(size_t)(b0 + nb) * 64 + o] =
                    sRED8[nb * 64 + o] + sRED8[256 + nb * 64 + o] + sBO[o];
            }

            if (++nb3 == 3) nb3 = 0;
        }
    }
}

extern "C" void kernel_launch(void* const* d_in, const int* in_sizes, int n_in,
                              void* d_out, int out_size)
{
    const float* node_embed = (const float*)d_in[0];
    const int*   start_idx  = (const int*)d_in[1];
    const int*   end_idx    = (const int*)d_in[2];
    /* d_in[3] seg_ids unused (structural) */
    const int*   pad_idx    = (const int*)d_in[4];
    const float* Wq         = (const float*)d_in[5];
    const float* bq         = (const float*)d_in[6];
    const float* Wk         = (const float*)d_in[7];
    /* d_in[8] bk unused (cancels in softmax) */
    const float* Wv         = (const float*)d_in[9];
    const float* bv         = (const float*)d_in[10];
    const float* Wo         = (const float*)d_in[11];
    const float* bo         = (const float*)d_in[12];
    float* out = (float*)d_out;

    int B = out_size / 64;

    cudaFuncSetAttribute(mha_state_encoder_kernel,
                         cudaFuncAttributeMaxDynamicSharedMemorySize, SMEM_BYTES);
    mha_state_encoder_kernel<<<GRID, NT, SMEM_BYTES>>>(
        node_embed, start_idx, end_idx, pad_idx,
        Wq, bq, Wk, Wv, bv, Wo, bo, out, B);
}

// round 12
// speedup vs baseline: 1.1448x; 1.0501x over previous
#include <cuda_runtime.h>
#include <cstdint>
#include <math.h>

// Round 11: R10 pipeline + consumer-side 8-batch amortization of P7/P8
// (sM double-buffered by group parity; WV/WO read once per 8 batches).

#define NT 384
#define GRID 148

typedef unsigned long long ull;

// shared memory float offsets
#define OFF_WKT   0        // [128][65]
#define OFF_WV    8320     // [64][128]
#define OFF_WO    16512    // [128][64]
#define OFF_BQ    24704
#define OFF_BV    24832
#define OFF_BO    24960
#define OFF_N     25024    // [3][4][20][68] = 16320 (triple-buffered node tiles)
#define OFF_V     41344    // [3][4][20] = 240
#define OFF_QK    41584    // [2][4][8][72] = 4608 (double-buffered qk)
#define OFF_RAW   46192    // [192][4] = 768 (producer-private)
#define OFF_Q     46960    // [128][4] = 512 (producer-private)
#define OFF_PART  47472    // [4][128][2] ull = 2048 floats (producer-private)
#define OFF_SC    49520    // [4][8][28] = 896 (consumer-private)
#define OFF_M     50416    // [2][4][8][72] = 4608 (consumer, parity-buffered)
#define OFF_CTX   55024    // [8][128] = 1024 (consumer-private)
#define OFF_RED8  56048    // [2][8][64] = 1024 (consumer-private)
#define SMEM_FLOATS 57072
#define SMEM_BYTES  (SMEM_FLOATS * 4)   // 228288 B  (cap 232448)

// named barrier ids
#define BFULL0 1   // +qb : producer(arrive 256) -> consumer(sync 128), total 384
#define BEQ0   3   // +qb : consumer(arrive) -> producer(sync)
#define BEN0   5   // +nb3: consumer(arrive) -> producer(sync)
#define BPROD  8   // producer-internal, 256
#define BCONS  9   // consumer-internal, 128

#define BAR_SYNC(id, cnt)   asm volatile("bar.sync %0, %1;"   :: "r"(id), "r"(cnt) : "memory")
#define BAR_ARRIVE(id, cnt) asm volatile("bar.arrive %0, %1;" :: "r"(id), "r"(cnt) : "memory")
#define CP_COMMIT()         asm volatile("cp.async.commit_group;" ::: "memory")
#define CP_WAIT1()          asm volatile("cp.async.wait_group 1;" ::: "memory")

__device__ __forceinline__ ull pk1(float a) {
    ull r; asm("mov.b64 %0, {%1,%1};" : "=l"(r) : "f"(a)); return r;
}
__device__ __forceinline__ void fma2(ull& d, ull a, ull b) {
    asm("fma.rn.f32x2 %0, %1, %2, %0;" : "+l"(d) : "l"(a), "l"(b));
}
__device__ __forceinline__ ull add2(ull a, ull b) {
    ull r; asm("add.rn.f32x2 %0, %1, %2;" : "=l"(r) : "l"(a), "l"(b)); return r;
}
__device__ __forceinline__ ull mul2(ull a, ull b) {
    ull r; asm("mul.rn.f32x2 %0, %1, %2;" : "=l"(r) : "l"(a), "l"(b)); return r;
}
__device__ __forceinline__ float2 upk(ull a) {
    float2 f; asm("mov.b64 {%0,%1}, %2;" : "=f"(f.x), "=f"(f.y) : "l"(a)); return f;
}

// issue 5x 16B cp.async for one group's node tile into buffer nbuf
__device__ __forceinline__ void issue_node_cp(unsigned int sbase, const float* ne,
                                              int b0, int nbuf, int t) {
    const float4* src = reinterpret_cast<const float4*>(ne) + (size_t)b0 * 320;
    #pragma unroll
    for (int kk = 0; kk < 5; ++kk) {
        int g   = t + kk * 256;
        int nb  = g / 320;
        int rem = g - nb * 320;
        unsigned int dstf = (unsigned int)(OFF_N + nbuf * 5440 + nb * 1360 +
                                           ((rem >> 4) * 17 + (rem & 15)) * 4);
        asm volatile("cp.async.ca.shared.global [%0], [%1], 16;"
                     :: "r"(sbase + dstf * 4), "l"(src + g) : "memory");
    }
}

__global__ void __launch_bounds__(NT, 1)
mha_state_encoder_kernel(const float* __restrict__ node_embed,
                         const int*   __restrict__ start_idx,
                         const int*   __restrict__ end_idx,
                         const int*   __restrict__ pad_idx,
                         const float* __restrict__ Wq, const float* __restrict__ bq,
                         const float* __restrict__ Wk,
                         const float* __restrict__ Wv, const float* __restrict__ bv,
                         const float* __restrict__ Wo, const float* __restrict__ bo,
                         float* __restrict__ out, int B)
{
    extern __shared__ float sm[];
    float* sWKT = sm + OFF_WKT;
    float* sWV  = sm + OFF_WV;
    float* sWO  = sm + OFF_WO;
    float* sBQ  = sm + OFF_BQ;
    float* sBV  = sm + OFF_BV;
    float* sBO  = sm + OFF_BO;
    float* sN   = sm + OFF_N;
    float* sV   = sm + OFF_V;
    float* sQK  = sm + OFF_QK;
    float* sRAW = sm + OFF_RAW;
    float* sSC  = sm + OFF_SC;
    float* sM   = sm + OFF_M;
    float* sCTX = sm + OFF_CTX;
    float* sRED8= sm + OFF_RED8;
    ull*   sQ2  = reinterpret_cast<ull*>(sm + OFF_Q);
    ull*   sPT  = reinterpret_cast<ull*>(sm + OFF_PART);

    unsigned int sbase;
    asm("{ .reg .u64 tt; cvta.to.shared.u64 tt, %1; cvt.u32.u64 %0, tt; }"
        : "=r"(sbase) : "l"(sm));

    const int t  = threadIdx.x;
    const int Qn = B >> 2;            // 4-batch groups
    const int q0 = blockIdx.x;

    // ---- stage weights (whole CTA) ----
    for (int i = t; i < 8192; i += NT) {
        int d = i >> 7, c = i & 127;
        sWKT[c * 65 + d] = Wk[i];
    }
    for (int i = t; i < 2048; i += NT) {
        reinterpret_cast<float4*>(sWV)[i] = reinterpret_cast<const float4*>(Wv)[i];
        reinterpret_cast<float4*>(sWO)[i] = reinterpret_cast<const float4*>(Wo)[i];
    }
    if (t < 128) { sBQ[t] = bq[t]; sBV[t] = bv[t]; }
    if (t < 64)  sBO[t] = bo[t];
    __syncthreads();   // ONLY whole-CTA sync; everything below is divergent teams

    if (t < 256) {
        // ======================= PRODUCER (256 threads) =======================
        const int cl = t & 63;
        const int rg = t >> 6;            // 0..3 row slices (48 rows each)
        float wq[96];                     // 48 rows x cols {cl, cl+64}
        {
            const float* src = Wq + (size_t)(rg * 48) * 128 + cl;
            #pragma unroll
            for (int i = 0; i < 24; ++i) {
                wq[4*i+0] = src[(size_t)(2*i)   * 128];
                wq[4*i+1] = src[(size_t)(2*i)   * 128 + 64];
                wq[4*i+2] = src[(size_t)(2*i+1) * 128];
                wq[4*i+3] = src[(size_t)(2*i+1) * 128 + 64];
            }
        }
        // gather geometry (threads 128..255): 4 nb x 2 wh x 16 dq = 128
        const int gg  = t - 128;
        const int gnb = gg & 3;
        const int gwh = (gg >> 2) & 1;
        const int gdq = gg >> 3;

        float4 pfG = make_float4(0.f, 0.f, 0.f, 0.f);
        int pfP = 0, gi_next = 0;

        if (q0 < Qn)        issue_node_cp(sbase, node_embed, q0 * 4, 0, t);
        CP_COMMIT();
        if (q0 + GRID < Qn) issue_node_cp(sbase, node_embed, (q0 + GRID) * 4, 1, t);
        CP_COMMIT();
        if (q0 < Qn) {
            if (t >= 128) {
                int gi = gwh ? end_idx[q0 * 4 + gnb] : start_idx[q0 * 4 + gnb];
                pfG = *reinterpret_cast<const float4*>(node_embed + (size_t)gi * 64 + gdq * 4);
                int qn = q0 + GRID;
                if (qn < Qn) gi_next = gwh ? end_idx[qn * 4 + gnb] : start_idx[qn * 4 + gnb];
            }
            if (t < 80) pfP = pad_idx[q0 * 80 + t];
        }

        int it = 0, nb3 = 0;
        for (int q = q0; q < Qn; q += GRID, ++it) {
            const int qb = it & 1;

            CP_WAIT1();   // this group's node tile landed

            if (t >= 128) {
                int r0 = 64 + gwh * 64 + gdq * 4;
                sRAW[(r0 + 0) * 4 + gnb] = pfG.x;
                sRAW[(r0 + 1) * 4 + gnb] = pfG.y;
                sRAW[(r0 + 2) * 4 + gnb] = pfG.z;
                sRAW[(r0 + 3) * 4 + gnb] = pfG.w;
            }
            if (t < 80) sV[nb3 * 80 + t] = (pfP >= 0) ? 1.0f : 0.0f;
            if (q + GRID < Qn) {
                if (t >= 128) {
                    pfG = *reinterpret_cast<const float4*>(node_embed + (size_t)gi_next * 64 + gdq * 4);
                    int qn2 = q + 2 * GRID;
                    if (qn2 < Qn) gi_next = gwh ? end_idx[qn2 * 4 + gnb] : start_idx[qn2 * 4 + gnb];
                }
                if (t < 80) pfP = pad_idx[(q + GRID) * 80 + t];
            }
            BAR_SYNC(BPROD, 256);

            // ---- P2: agg (column sums) ----
            if (t < 64) {
                int nb = t >> 4, dq = t & 15;
                const float4* col = reinterpret_cast<const float4*>(sN + nb3 * 5440 + nb * 1360) + dq;
                float ax = 0.f, ay = 0.f, az = 0.f, aw = 0.f;
                #pragma unroll
                for (int j = 0; j < 20; ++j) {
                    float4 x = col[j * 17];
                    ax += x.x; ay += x.y; az += x.z; aw += x.w;
                }
                int r0 = dq * 4;
                sRAW[(r0 + 0) * 4 + nb] = ax;
                sRAW[(r0 + 1) * 4 + nb] = ay;
                sRAW[(r0 + 2) * 4 + nb] = az;
                sRAW[(r0 + 3) * 4 + nb] = aw;
            }
            BAR_SYNC(BPROD, 256);

            // ---- P3a: q partials (f32x2, 4 row slices x 2 cols) ----
            {
                const ulonglong2* pR = reinterpret_cast<const ulonglong2*>(sRAW) + rg * 48;
                ull a0 = 0, a1 = 0, b0u = 0, b1u = 0;
                #pragma unroll
                for (int i = 0; i < 24; ++i) {
                    ulonglong2 x = pR[2 * i];
                    ulonglong2 y = pR[2 * i + 1];
                    ull w0 = pk1(wq[4*i+0]), w1 = pk1(wq[4*i+1]);
                    ull w2 = pk1(wq[4*i+2]), w3 = pk1(wq[4*i+3]);
                    fma2(a0,  w0, x.x); fma2(a1,  w0, x.y);
                    fma2(b0u, w1, x.x); fma2(b1u, w1, x.y);
                    fma2(a0,  w2, y.x); fma2(a1,  w2, y.y);
                    fma2(b0u, w3, y.x); fma2(b1u, w3, y.y);
                }
                ull* dA = sPT + rg * 256 + cl * 2;
                dA[0] = a0; dA[1] = a1;
                ull* dB = sPT + rg * 256 + (cl + 64) * 2;
                dB[0] = b0u; dB[1] = b1u;
            }
            BAR_SYNC(BPROD, 256);

            // ---- P3b: combine slices + bias + 0.25 scale -> sQ ----
            {
                int c = t >> 1, pp = t & 1;
                int o = c * 2 + pp;
                ull v = add2(add2(sPT[o], sPT[256 + o]),
                             add2(sPT[512 + o], sPT[768 + o]));
                v = add2(v, pk1(sBQ[c]));
                v = mul2(v, pk1(0.25f));
                sQ2[c * 2 + pp] = v;
            }
            BAR_SYNC(BPROD, 256);

            // ---- P4: qk -> sQK[qb] ----
            if (it >= 2) BAR_SYNC(BEQ0 + qb, 384);
            #pragma unroll
            for (int p = 0; p < 2; ++p) {
                int v2 = t + p * 256;
                int h = v2 >> 6, d = v2 & 63;
                const float* wkb = sWKT + h * 16 * 65 + d;
                const ulonglong2* q2 = reinterpret_cast<const ulonglong2*>(sQ2) + h * 16;
                ull a01 = 0, a23 = 0;
                #pragma unroll
                for (int i = 0; i < 16; ++i) {
                    ull wp = pk1(wkb[i * 65]);
                    ulonglong2 qv = q2[i];
                    fma2(a01, wp, qv.x);
                    fma2(a23, wp, qv.y);
                }
                float2 f01 = upk(a01), f23 = upk(a23);
                float* dst = sQK + qb * 2304 + h * 72 + d;
                dst[0 * 576] = f01.x; dst[1 * 576] = f01.y;
                dst[2 * 576] = f23.x; dst[3 * 576] = f23.y;
            }
            BAR_ARRIVE(BFULL0 + qb, 384);

            // ---- issue node cp.async for group q+2*GRID ----
            {
                int nb3p2 = nb3 + 2; if (nb3p2 >= 3) nb3p2 -= 3;
                if (q + 2 * GRID < Qn) {
                    if (it >= 1) BAR_SYNC(BEN0 + nb3p2, 384);
                    issue_node_cp(sbase, node_embed, (q + 2 * GRID) * 4, nb3p2, t);
                }
                CP_COMMIT();
            }
            if (++nb3 == 3) nb3 = 0;
        }
    } else {
        // ======================= CONSUMER (128 threads) =======================
        const int u = t - 256;
        int it = 0, nb3 = 0;
        int b0_prev = 0;
        for (int q = q0; q < Qn; q += GRID, ++it) {
            const int b0 = q * 4;
            const int qb  = it & 1;
            const int par = it & 1;            // sM parity buffer
            const float* nbase = sN + nb3 * 5440;
            const float* vbase = sV + nb3 * 80;
            const float* qkB   = sQK + qb * 2304;
            float* sMp = sM + par * 2304;

            BAR_SYNC(BFULL0 + qb, 384);   // qk + nodes + valid ready

            // ---- P5: scores + inline mask (160 tasks) ----
            for (int v = u; v < 160; v += 128) {
                int nb = v / 40;
                int r  = v - nb * 40;
                int j  = r >> 1;
                int hh = r & 1;
                const float4* n4  = reinterpret_cast<const float4*>(nbase + nb * 1360 + j * 68);
                const float*  qkb = qkB + nb * 576 + (hh * 4) * 72;
                float s0 = 0.f, s1 = 0.f, s2 = 0.f, s3 = 0.f, rsum = 0.f;
                #pragma unroll
                for (int k = 0; k < 16; ++k) {
                    float4 x  = n4[k];
                    rsum += (x.x + x.y) + (x.z + x.w);
                    float4 a0 = *reinterpret_cast<const float4*>(qkb + 0 * 72 + k * 4);
                    float4 a1 = *reinterpret_cast<const float4*>(qkb + 1 * 72 + k * 4);
                    float4 a2 = *reinterpret_cast<const float4*>(qkb + 2 * 72 + k * 4);
                    float4 a3 = *reinterpret_cast<const float4*>(qkb + 3 * 72 + k * 4);
                    s0 = fmaf(a0.x,x.x,s0); s0 = fmaf(a0.y,x.y,s0); s0 = fmaf(a0.z,x.z,s0); s0 = fmaf(a0.w,x.w,s0);
                    s1 = fmaf(a1.x,x.x,s1); s1 = fmaf(a1.y,x.y,s1); s1 = fmaf(a1.z,x.z,s1); s1 = fmaf(a1.w,x.w,s1);
                    s2 = fmaf(a2.x,x.x,s2); s2 = fmaf(a2.y,x.y,s2); s2 = fmaf(a2.z,x.z,s2); s2 = fmaf(a2.w,x.w,s2);
                    s3 = fmaf(a3.x,x.x,s3); s3 = fmaf(a3.y,x.y,s3); s3 = fmaf(a3.z,x.z,s3); s3 = fmaf(a3.w,x.w,s3);
                }
                float msk = (vbase[nb * 20 + j] == 0.f || rsum == 0.f) ? -1e9f : 0.f;
                float* dst = sSC + nb * 224 + (hh * 4) * 28 + j;
                dst[0 * 28] = s0 + msk;
                dst[1 * 28] = s1 + msk;
                dst[2 * 28] = s2 + msk;
                dst[3 * 28] = s3 + msk;
            }
            BAR_SYNC(BCONS, 128);
            BAR_ARRIVE(BEQ0 + qb, 384);    // done with sQK[qb]

            // ---- softmax: 32 rows x 4 lanes ----
            {
                int row = u >> 2, j0 = u & 3;
                int nb = row >> 3, h = row & 7;
                float* base = sSC + nb * 224 + h * 28;
                const float* vd = vbase + nb * 20;
                float x0 = base[j0], x1 = base[j0+4], x2 = base[j0+8], x3 = base[j0+12], x4 = base[j0+16];
                float mx = fmaxf(fmaxf(fmaxf(x0, x1), fmaxf(x2, x3)), x4);
                mx = fmaxf(mx, __shfl_xor_sync(0xffffffffu, mx, 1));
                mx = fmaxf(mx, __shfl_xor_sync(0xffffffffu, mx, 2));
                float e0 = __expf(x0 - mx), e1 = __expf(x1 - mx), e2 = __expf(x2 - mx);
                float e3 = __expf(x3 - mx), e4 = __expf(x4 - mx);
                float s = ((e0 + e1) + (e2 + e3)) + e4;
                s += __shfl_xor_sync(0xffffffffu, s, 1);
                s += __shfl_xor_sync(0xffffffffu, s, 2);
                float inv = __fdividef(1.f, s);
                base[j0]      = e0 * inv * vd[j0];
                base[j0 + 4]  = e1 * inv * vd[j0 + 4];
                base[j0 + 8]  = e2 * inv * vd[j0 + 8];
                base[j0 + 12] = e3 * inv * vd[j0 + 12];
                base[j0 + 16] = e4 * inv * vd[j0 + 16];
            }
            BAR_SYNC(BCONS, 128);

            // ---- P6: m (4 heads/thread) -> sM[par] ----
            {
                int nb = u >> 5, dq = (u >> 1) & 15, hg = u & 1;
                const float4* n4 = reinterpret_cast<const float4*>(nbase + nb * 1360) + dq;
                const float* a0 = sSC + nb * 224 + (hg * 4 + 0) * 28;
                const float* a1 = sSC + nb * 224 + (hg * 4 + 1) * 28;
                const float* a2 = sSC + nb * 224 + (hg * 4 + 2) * 28;
                const float* a3 = sSC + nb * 224 + (hg * 4 + 3) * 28;
                float4 m0 = make_float4(0,0,0,0), m1 = make_float4(0,0,0,0);
                float4 m2 = make_float4(0,0,0,0), m3 = make_float4(0,0,0,0);
                #pragma unroll
                for (int jq = 0; jq < 5; ++jq) {
                    float4 w0 = *reinterpret_cast<const float4*>(a0 + jq * 4);
                    float4 w1 = *reinterpret_cast<const float4*>(a1 + jq * 4);
                    float4 w2 = *reinterpret_cast<const float4*>(a2 + jq * 4);
                    float4 w3 = *reinterpret_cast<const float4*>(a3 + jq * 4);
                    #pragma unroll
                    for (int jj = 0; jj < 4; ++jj) {
                        float4 x = n4[(jq * 4 + jj) * 17];
                        float c0 = jj == 0 ? w0.x : jj == 1 ? w0.y : jj == 2 ? w0.z : w0.w;
                        float c1 = jj == 0 ? w1.x : jj == 1 ? w1.y : jj == 2 ? w1.z : w1.w;
                        float c2 = jj == 0 ? w2.x : jj == 1 ? w2.y : jj == 2 ? w2.z : w2.w;
                        float c3 = jj == 0 ? w3.x : jj == 1 ? w3.y : jj == 2 ? w3.z : w3.w;
                        m0.x = fmaf(c0,x.x,m0.x); m0.y = fmaf(c0,x.y,m0.y); m0.z = fmaf(c0,x.z,m0.z); m0.w = fmaf(c0,x.w,m0.w);
                        m1.x = fmaf(c1,x.x,m1.x); m1.y = fmaf(c1,x.y,m1.y); m1.z = fmaf(c1,x.z,m1.z); m1.w = fmaf(c1,x.w,m1.w);
                        m2.x = fmaf(c2,x.x,m2.x); m2.y = fmaf(c2,x.y,m2.y); m2.z = fmaf(c2,x.z,m2.z); m2.w = fmaf(c2,x.w,m2.w);
                        m3.x = fmaf(c3,x.x,m3.x); m3.y = fmaf(c3,x.y,m3.y); m3.z = fmaf(c3,x.z,m3.z); m3.w = fmaf(c3,x.w,m3.w);
                    }
                }
                float* mb = sMp + nb * 576 + (hg * 4) * 72 + dq * 4;
                *reinterpret_cast<float4*>(mb + 0 * 72) = m0;
                *reinterpret_cast<float4*>(mb + 1 * 72) = m1;
                *reinterpret_cast<float4*>(mb + 2 * 72) = m2;
                *reinterpret_cast<float4*>(mb + 3 * 72) = m3;
            }
            BAR_SYNC(BCONS, 128);
            BAR_ARRIVE(BEN0 + nb3, 384);   // done with sN/sV buffer

            if (par == 1) {
                // ---- P7: ctx for 8 batches (2 buffered groups) ----
                {
                    int cc = u, h = u >> 4;
                    float acc[8] = {0,0,0,0,0,0,0,0};
                    #pragma unroll
                    for (int kq = 0; kq < 16; ++kq) {
                        int d = kq * 4;
                        float w0 = sWV[(d+0)*128 + cc], w1 = sWV[(d+1)*128 + cc];
                        float w2 = sWV[(d+2)*128 + cc], w3 = sWV[(d+3)*128 + cc];
                        #pragma unroll
                        for (int i8 = 0; i8 < 8; ++i8) {
                            const float* mg = sM + (i8 >> 2) * 2304 + (i8 & 3) * 576 + h * 72 + d;
                            float4 m = *reinterpret_cast<const float4*>(mg);
                            acc[i8] = fmaf(w0, m.x, fmaf(w1, m.y, fmaf(w2, m.z, fmaf(w3, m.w, acc[i8]))));
                        }
                    }
                    float bvv = sBV[cc];
                    #pragma unroll
                    for (int i8 = 0; i8 < 8; ++i8)
                        sCTX[i8 * 128 + cc] = acc[i8] + bvv;
                }
                BAR_SYNC(BCONS, 128);

                // ---- P8: out for 8 batches (2-way c split) ----
                {
                    int o = u & 63, cg = u >> 6, c0 = cg * 64;
                    float acc[8] = {0,0,0,0,0,0,0,0};
                    #pragma unroll
                    for (int kq = 0; kq < 16; ++kq) {
                        int c = c0 + kq * 4;
                        float w0 = sWO[(c+0)*64 + o], w1 = sWO[(c+1)*64 + o];
                        float w2 = sWO[(c+2)*64 + o], w3 = sWO[(c+3)*64 + o];
                        #pragma unroll
                        for (int i8 = 0; i8 < 8; ++i8) {
                            float4 x = *reinterpret_cast<const float4*>(sCTX + i8 * 128 + c);
                            acc[i8] = fmaf(w0, x.x, fmaf(w1, x.y, fmaf(w2, x.z, fmaf(w3, x.w, acc[i8]))));
                        }
                    }
                    #pragma unroll
                    for (int i8 = 0; i8 < 8; ++i8)
                        sRED8[cg * 512 + i8 * 64 + o] = acc[i8];
                }
                BAR_SYNC(BCONS, 128);
                #pragma unroll
                for (int p = 0; p < 4; ++p) {
                    int e  = u + p * 128;
                    int i8 = e >> 6, o = e & 63;
                    int bb = (i8 < 4) ? b0_prev : b0;
                    out[(size_t)(bb + (i8 & 3)) * 64 + o] =
                        sRED8[i8 * 64 + o] + sRED8[512 + i8 * 64 + o] + sBO[o];
                }
            } else {
                b0_prev = b0;
            }

            if (++nb3 == 3) nb3 = 0;
        }

        // ---- flush: odd group count leaves sM[0] pending ----
        if (it & 1) {
            {
                int cc = u, h = u >> 4;
                float acc[4] = {0,0,0,0};
                #pragma unroll
                for (int kq = 0; kq < 16; ++kq) {
                    int d = kq * 4;
                    float w0 = sWV[(d+0)*128 + cc], w1 = sWV[(d+1)*128 + cc];
                    float w2 = sWV[(d+2)*128 + cc], w3 = sWV[(d+3)*128 + cc];
                    #pragma unroll
                    for (int nb = 0; nb < 4; ++nb) {
                        float4 m = *reinterpret_cast<const float4*>(sM + nb * 576 + h * 72 + d);
                        acc[nb] = fmaf(w0, m.x, fmaf(w1, m.y, fmaf(w2, m.z, fmaf(w3, m.w, acc[nb]))));
                    }
                }
                float bvv = sBV[cc];
                #pragma unroll
                for (int nb = 0; nb < 4; ++nb)
                    sCTX[nb * 128 + cc] = acc[nb] + bvv;
            }
            BAR_SYNC(BCONS, 128);
            {
                int o = u & 63, cg = u >> 6, c0 = cg * 64;
                float acc[4] = {0,0,0,0};
                #pragma unroll
                for (int kq = 0; kq < 16; ++kq) {
                    int c = c0 + kq * 4;
                    float w0 = sWO[(c+0)*64 + o], w1 = sWO[(c+1)*64 + o];
                    float w2 = sWO[(c+2)*64 + o], w3 = sWO[(c+3)*64 + o];
                    #pragma unroll
                    for (int nb = 0; nb < 4; ++nb) {
                        float4 x = *reinterpret_cast<const float4*>(sCTX + nb * 128 + c);
                        acc[nb] = fmaf(w0, x.x, fmaf(w1, x.y, fmaf(w2, x.z, fmaf(w3, x.w, acc[nb]))));
                    }
                }
                #pragma unroll
                for (int nb = 0; nb < 4; ++nb)
                    sRED8[cg * 512 + nb * 64 + o] = acc[nb];
            }
            BAR_SYNC(BCONS, 128);
            #pragma unroll
            for (int p = 0; p < 2; ++p) {
                int e  = u + p * 128;
                int nb = e >> 6, o = e & 63;
                out[(size_t)(b0_prev + nb) * 64 + o] =
                    sRED8[nb * 64 + o] + sRED8[512 + nb * 64 + o] + sBO[o];
            }
        }
    }
}

extern "C" void kernel_launch(void* const* d_in, const int* in_sizes, int n_in,
                              void* d_out, int out_size)
{
    const float* node_embed = (const float*)d_in[0];
    const int*   start_idx  = (const int*)d_in[1];
    const int*   end_idx    = (const int*)d_in[2];
    /* d_in[3] seg_ids unused (structural) */
    const int*   pad_idx    = (const int*)d_in[4];
    const float* Wq         = (const float*)d_in[5];
    const float* bq         = (const float*)d_in[6];
    const float* Wk         = (const float*)d_in[7];
    /* d_in[8] bk unused (cancels in softmax) */
    const float* Wv         = (const float*)d_in[9];
    const float* bv         = (const float*)d_in[10];
    const float* Wo         = (const float*)d_in[11];
    const float* bo         = (const float*)d_in[12];
    float* out = (float*)d_out;

    int B = out_size / 64;

    cudaFuncSetAttribute(mha_state_encoder_kernel,
                         cudaFuncAttributeMaxDynamicSharedMemorySize, SMEM_BYTES);
    mha_state_encoder_kernel<<<GRID, NT, SMEM_BYTES>>>(
        node_embed, start_idx, end_idx, pad_idx,
        Wq, bq, Wk, Wv, bv, Wo, bo, out, B);
}

// round 13
// speedup vs baseline: 1.3348x; 1.1659x over previous
#include <cuda_runtime.h>
#include <cstdint>
#include <math.h>

// Round 12: R11 pipeline + consumer f32x2 (P5/P6/P7/P8) + P5 remapped to
// 80 tasks x 8 heads (node rows read once, no thread imbalance).

#define NT 384
#define GRID 148

typedef unsigned long long ull;

// shared memory float offsets
#define OFF_WKT   0        // [128][65]
#define OFF_WV    8320     // [64][128]
#define OFF_WO    16512    // [128][64]
#define OFF_BQ    24704
#define OFF_BV    24832
#define OFF_BO    24960
#define OFF_N     25024    // [3][4][20][68] = 16320
#define OFF_V     41344    // [3][4][20] = 240
#define OFF_QK    41584    // [2][4][8][72] = 4608
#define OFF_RAW   46192    // [192][4] = 768
#define OFF_Q     46960    // [128][4] = 512
#define OFF_PART  47472    // [4][128][2] ull = 2048 floats
#define OFF_SC    49520    // [4][8][28] = 896
#define OFF_M     50416    // [2][4][8][72] = 4608 (parity-buffered)
#define OFF_CTX   55024    // [8][128] = 1024
#define OFF_RED8  56048    // [2][8][64] = 1024
#define SMEM_FLOATS 57072
#define SMEM_BYTES  (SMEM_FLOATS * 4)   // 228288 B

// named barrier ids
#define BFULL0 1
#define BEQ0   3
#define BEN0   5
#define BPROD  8
#define BCONS  9

#define BAR_SYNC(id, cnt)   asm volatile("bar.sync %0, %1;"   :: "r"(id), "r"(cnt) : "memory")
#define BAR_ARRIVE(id, cnt) asm volatile("bar.arrive %0, %1;" :: "r"(id), "r"(cnt) : "memory")
#define CP_COMMIT()         asm volatile("cp.async.commit_group;" ::: "memory")
#define CP_WAIT1()          asm volatile("cp.async.wait_group 1;" ::: "memory")

__device__ __forceinline__ ull pk1(float a) {
    ull r; asm("mov.b64 %0, {%1,%1};" : "=l"(r) : "f"(a)); return r;
}
__device__ __forceinline__ ull pk2(float a, float b) {
    ull r; asm("mov.b64 %0, {%1,%2};" : "=l"(r) : "f"(a), "f"(b)); return r;
}
__device__ __forceinline__ void fma2(ull& d, ull a, ull b) {
    asm("fma.rn.f32x2 %0, %1, %2, %0;" : "+l"(d) : "l"(a), "l"(b));
}
__device__ __forceinline__ ull add2(ull a, ull b) {
    ull r; asm("add.rn.f32x2 %0, %1, %2;" : "=l"(r) : "l"(a), "l"(b)); return r;
}
__device__ __forceinline__ ull mul2(ull a, ull b) {
    ull r; asm("mul.rn.f32x2 %0, %1, %2;" : "=l"(r) : "l"(a), "l"(b)); return r;
}
__device__ __forceinline__ float2 upk(ull a) {
    float2 f; asm("mov.b64 {%0,%1}, %2;" : "=f"(f.x), "=f"(f.y) : "l"(a)); return f;
}

__device__ __forceinline__ void issue_node_cp(unsigned int sbase, const float* ne,
                                              int b0, int nbuf, int t) {
    const float4* src = reinterpret_cast<const float4*>(ne) + (size_t)b0 * 320;
    #pragma unroll
    for (int kk = 0; kk < 5; ++kk) {
        int g   = t + kk * 256;
        int nb  = g / 320;
        int rem = g - nb * 320;
        unsigned int dstf = (unsigned int)(OFF_N + nbuf * 5440 + nb * 1360 +
                                           ((rem >> 4) * 17 + (rem & 15)) * 4);
        asm volatile("cp.async.ca.shared.global [%0], [%1], 16;"
                     :: "r"(sbase + dstf * 4), "l"(src + g) : "memory");
    }
}

__global__ void __launch_bounds__(NT, 1)
mha_state_encoder_kernel(const float* __restrict__ node_embed,
                         const int*   __restrict__ start_idx,
                         const int*   __restrict__ end_idx,
                         const int*   __restrict__ pad_idx,
                         const float* __restrict__ Wq, const float* __restrict__ bq,
                         const float* __restrict__ Wk,
                         const float* __restrict__ Wv, const float* __restrict__ bv,
                         const float* __restrict__ Wo, const float* __restrict__ bo,
                         float* __restrict__ out, int B)
{
    extern __shared__ float sm[];
    float* sWKT = sm + OFF_WKT;
    float* sWV  = sm + OFF_WV;
    float* sWO  = sm + OFF_WO;
    float* sBQ  = sm + OFF_BQ;
    float* sBV  = sm + OFF_BV;
    float* sBO  = sm + OFF_BO;
    float* sN   = sm + OFF_N;
    float* sV   = sm + OFF_V;
    float* sQK  = sm + OFF_QK;
    float* sRAW = sm + OFF_RAW;
    float* sSC  = sm + OFF_SC;
    float* sM   = sm + OFF_M;
    float* sCTX = sm + OFF_CTX;
    float* sRED8= sm + OFF_RED8;
    ull*   sQ2  = reinterpret_cast<ull*>(sm + OFF_Q);
    ull*   sPT  = reinterpret_cast<ull*>(sm + OFF_PART);

    unsigned int sbase;
    asm("{ .reg .u64 tt; cvta.to.shared.u64 tt, %1; cvt.u32.u64 %0, tt; }"
        : "=r"(sbase) : "l"(sm));

    const int t  = threadIdx.x;
    const int Qn = B >> 2;
    const int q0 = blockIdx.x;

    // ---- stage weights (whole CTA) ----
    for (int i = t; i < 8192; i += NT) {
        int d = i >> 7, c = i & 127;
        sWKT[c * 65 + d] = Wk[i];
    }
    for (int i = t; i < 2048; i += NT) {
        reinterpret_cast<float4*>(sWV)[i] = reinterpret_cast<const float4*>(Wv)[i];
        reinterpret_cast<float4*>(sWO)[i] = reinterpret_cast<const float4*>(Wo)[i];
    }
    if (t < 128) { sBQ[t] = bq[t]; sBV[t] = bv[t]; }
    if (t < 64)  sBO[t] = bo[t];
    __syncthreads();

    if (t < 256) {
        // ======================= PRODUCER (256 threads) =======================
        const int cl = t & 63;
        const int rg = t >> 6;
        float wq[96];
        {
            const float* src = Wq + (size_t)(rg * 48) * 128 + cl;
            #pragma unroll
            for (int i = 0; i < 24; ++i) {
                wq[4*i+0] = src[(size_t)(2*i)   * 128];
                wq[4*i+1] = src[(size_t)(2*i)   * 128 + 64];
                wq[4*i+2] = src[(size_t)(2*i+1) * 128];
                wq[4*i+3] = src[(size_t)(2*i+1) * 128 + 64];
            }
        }
        const int gg  = t - 128;
        const int gnb = gg & 3;
        const int gwh = (gg >> 2) & 1;
        const int gdq = gg >> 3;

        float4 pfG = make_float4(0.f, 0.f, 0.f, 0.f);
        int pfP = 0, gi_next = 0;

        if (q0 < Qn)        issue_node_cp(sbase, node_embed, q0 * 4, 0, t);
        CP_COMMIT();
        if (q0 + GRID < Qn) issue_node_cp(sbase, node_embed, (q0 + GRID) * 4, 1, t);
        CP_COMMIT();
        if (q0 < Qn) {
            if (t >= 128) {
                int gi = gwh ? end_idx[q0 * 4 + gnb] : start_idx[q0 * 4 + gnb];
                pfG = *reinterpret_cast<const float4*>(node_embed + (size_t)gi * 64 + gdq * 4);
                int qn = q0 + GRID;
                if (qn < Qn) gi_next = gwh ? end_idx[qn * 4 + gnb] : start_idx[qn * 4 + gnb];
            }
            if (t < 80) pfP = pad_idx[q0 * 80 + t];
        }

        int it = 0, nb3 = 0;
        for (int q = q0; q < Qn; q += GRID, ++it) {
            const int qb = it & 1;

            CP_WAIT1();

            if (t >= 128) {
                int r0 = 64 + gwh * 64 + gdq * 4;
                sRAW[(r0 + 0) * 4 + gnb] = pfG.x;
                sRAW[(r0 + 1) * 4 + gnb] = pfG.y;
                sRAW[(r0 + 2) * 4 + gnb] = pfG.z;
                sRAW[(r0 + 3) * 4 + gnb] = pfG.w;
            }
            if (t < 80) sV[nb3 * 80 + t] = (pfP >= 0) ? 1.0f : 0.0f;
            if (q + GRID < Qn) {
                if (t >= 128) {
                    pfG = *reinterpret_cast<const float4*>(node_embed + (size_t)gi_next * 64 + gdq * 4);
                    int qn2 = q + 2 * GRID;
                    if (qn2 < Qn) gi_next = gwh ? end_idx[qn2 * 4 + gnb] : start_idx[qn2 * 4 + gnb];
                }
                if (t < 80) pfP = pad_idx[(q + GRID) * 80 + t];
            }
            BAR_SYNC(BPROD, 256);

            // ---- P2: agg (column sums, f32x2) ----
            if (t < 64) {
                int nb = t >> 4, dq = t & 15;
                const ulonglong2* col = reinterpret_cast<const ulonglong2*>(sN + nb3 * 5440 + nb * 1360) + dq;
                ull s01 = 0, s23 = 0;
                #pragma unroll
                for (int j = 0; j < 20; ++j) {
                    ulonglong2 x = col[j * 17];
                    s01 = add2(s01, x.x);
                    s23 = add2(s23, x.y);
                }
                float2 a01 = upk(s01), a23 = upk(s23);
                int r0 = dq * 4;
                sRAW[(r0 + 0) * 4 + nb] = a01.x;
                sRAW[(r0 + 1) * 4 + nb] = a01.y;
                sRAW[(r0 + 2) * 4 + nb] = a23.x;
                sRAW[(r0 + 3) * 4 + nb] = a23.y;
            }
            BAR_SYNC(BPROD, 256);

            // ---- P3a: q partials ----
            {
                const ulonglong2* pR = reinterpret_cast<const ulonglong2*>(sRAW) + rg * 48;
                ull a0 = 0, a1 = 0, b0u = 0, b1u = 0;
                #pragma unroll
                for (int i = 0; i < 24; ++i) {
                    ulonglong2 x = pR[2 * i];
                    ulonglong2 y = pR[2 * i + 1];
                    ull w0 = pk1(wq[4*i+0]), w1 = pk1(wq[4*i+1]);
                    ull w2 = pk1(wq[4*i+2]), w3 = pk1(wq[4*i+3]);
                    fma2(a0,  w0, x.x); fma2(a1,  w0, x.y);
                    fma2(b0u, w1, x.x); fma2(b1u, w1, x.y);
                    fma2(a0,  w2, y.x); fma2(a1,  w2, y.y);
                    fma2(b0u, w3, y.x); fma2(b1u, w3, y.y);
                }
                ull* dA = sPT + rg * 256 + cl * 2;
                dA[0] = a0; dA[1] = a1;
                ull* dB = sPT + rg * 256 + (cl + 64) * 2;
                dB[0] = b0u; dB[1] = b1u;
            }
            BAR_SYNC(BPROD, 256);

            // ---- P3b: combine + bias + 0.25 ----
            {
                int c = t >> 1, pp = t & 1;
                int o = c * 2 + pp;
                ull v = add2(add2(sPT[o], sPT[256 + o]),
                             add2(sPT[512 + o], sPT[768 + o]));
                v = add2(v, pk1(sBQ[c]));
                v = mul2(v, pk1(0.25f));
                sQ2[c * 2 + pp] = v;
            }
            BAR_SYNC(BPROD, 256);

            // ---- P4: qk -> sQK[qb] ----
            if (it >= 2) BAR_SYNC(BEQ0 + qb, 384);
            #pragma unroll
            for (int p = 0; p < 2; ++p) {
                int v2 = t + p * 256;
                int h = v2 >> 6, d = v2 & 63;
                const float* wkb = sWKT + h * 16 * 65 + d;
                const ulonglong2* q2 = reinterpret_cast<const ulonglong2*>(sQ2) + h * 16;
                ull a01 = 0, a23 = 0;
                #pragma unroll
                for (int i = 0; i < 16; ++i) {
                    ull wp = pk1(wkb[i * 65]);
                    ulonglong2 qv = q2[i];
                    fma2(a01, wp, qv.x);
                    fma2(a23, wp, qv.y);
                }
                float2 f01 = upk(a01), f23 = upk(a23);
                float* dst = sQK + qb * 2304 + h * 72 + d;
                dst[0 * 576] = f01.x; dst[1 * 576] = f01.y;
                dst[2 * 576] = f23.x; dst[3 * 576] = f23.y;
            }
            BAR_ARRIVE(BFULL0 + qb, 384);

            // ---- issue node cp.async for group q+2*GRID ----
            {
                int nb3p2 = nb3 + 2; if (nb3p2 >= 3) nb3p2 -= 3;
                if (q + 2 * GRID < Qn) {
                    if (it >= 1) BAR_SYNC(BEN0 + nb3p2, 384);
                    issue_node_cp(sbase, node_embed, (q + 2 * GRID) * 4, nb3p2, t);
                }
                CP_COMMIT();
            }
            if (++nb3 == 3) nb3 = 0;
        }
    } else {
        // ======================= CONSUMER (128 threads) =======================
        const int u = t - 256;
        int it = 0, nb3 = 0;
        int b0_prev = 0;
        for (int q = q0; q < Qn; q += GRID, ++it) {
            const int b0 = q * 4;
            const int qb  = it & 1;
            const int par = it & 1;
            const float* nbase = sN + nb3 * 5440;
            const float* vbase = sV + nb3 * 80;
            const float* qkB   = sQK + qb * 2304;
            float* sMp = sM + par * 2304;

            BAR_SYNC(BFULL0 + qb, 384);

            // ---- P5: 80 tasks (nb,j) x 8 heads, f32x2 ----
            if (u < 80) {
                int nb = u / 20, j = u - nb * 20;
                const ulonglong2* n2 = reinterpret_cast<const ulonglong2*>(nbase + nb * 1360 + j * 68);
                const float* qkb = qkB + nb * 576;
                ull acc0 = 0, acc1 = 0, acc2 = 0, acc3 = 0;
                ull acc4 = 0, acc5 = 0, acc6 = 0, acc7 = 0;
                ull rs = 0;
                #pragma unroll
                for (int k = 0; k < 16; ++k) {
                    ulonglong2 x = n2[k];
                    rs = add2(rs, add2(x.x, x.y));
                    ulonglong2 q0v = *reinterpret_cast<const ulonglong2*>(qkb + 0 * 72 + k * 4);
                    ulonglong2 q1v = *reinterpret_cast<const ulonglong2*>(qkb + 1 * 72 + k * 4);
                    ulonglong2 q2v = *reinterpret_cast<const ulonglong2*>(qkb + 2 * 72 + k * 4);
                    ulonglong2 q3v = *reinterpret_cast<const ulonglong2*>(qkb + 3 * 72 + k * 4);
                    ulonglong2 q4v = *reinterpret_cast<const ulonglong2*>(qkb + 4 * 72 + k * 4);
                    ulonglong2 q5v = *reinterpret_cast<const ulonglong2*>(qkb + 5 * 72 + k * 4);
                    ulonglong2 q6v = *reinterpret_cast<const ulonglong2*>(qkb + 6 * 72 + k * 4);
                    ulonglong2 q7v = *reinterpret_cast<const ulonglong2*>(qkb + 7 * 72 + k * 4);
                    fma2(acc0, q0v.x, x.x); fma2(acc0, q0v.y, x.y);
                    fma2(acc1, q1v.x, x.x); fma2(acc1, q1v.y, x.y);
                    fma2(acc2, q2v.x, x.x); fma2(acc2, q2v.y, x.y);
                    fma2(acc3, q3v.x, x.x); fma2(acc3, q3v.y, x.y);
                    fma2(acc4, q4v.x, x.x); fma2(acc4, q4v.y, x.y);
                    fma2(acc5, q5v.x, x.x); fma2(acc5, q5v.y, x.y);
                    fma2(acc6, q6v.x, x.x); fma2(acc6, q6v.y, x.y);
                    fma2(acc7, q7v.x, x.x); fma2(acc7, q7v.y, x.y);
                }
                float2 rf = upk(rs);
                float rsum = rf.x + rf.y;
                float msk = (vbase[nb * 20 + j] == 0.f || rsum == 0.f) ? -1e9f : 0.f;
                float* dst = sSC + nb * 224 + j;
                float2 f;
                f = upk(acc0); dst[0 * 28] = f.x + f.y + msk;
                f = upk(acc1); dst[1 * 28] = f.x + f.y + msk;
                f = upk(acc2); dst[2 * 28] = f.x + f.y + msk;
                f = upk(acc3); dst[3 * 28] = f.x + f.y + msk;
                f = upk(acc4); dst[4 * 28] = f.x + f.y + msk;
                f = upk(acc5); dst[5 * 28] = f.x + f.y + msk;
                f = upk(acc6); dst[6 * 28] = f.x + f.y + msk;
                f = upk(acc7); dst[7 * 28] = f.x + f.y + msk;
            }
            BAR_SYNC(BCONS, 128);
            BAR_ARRIVE(BEQ0 + qb, 384);

            // ---- softmax: 32 rows x 4 lanes ----
            {
                int row = u >> 2, j0 = u & 3;
                int nb = row >> 3, h = row & 7;
                float* base = sSC + nb * 224 + h * 28;
                const float* vd = vbase + nb * 20;
                float x0 = base[j0], x1 = base[j0+4], x2 = base[j0+8], x3 = base[j0+12], x4 = base[j0+16];
                float mx = fmaxf(fmaxf(fmaxf(x0, x1), fmaxf(x2, x3)), x4);
                mx = fmaxf(mx, __shfl_xor_sync(0xffffffffu, mx, 1));
                mx = fmaxf(mx, __shfl_xor_sync(0xffffffffu, mx, 2));
                float e0 = __expf(x0 - mx), e1 = __expf(x1 - mx), e2 = __expf(x2 - mx);
                float e3 = __expf(x3 - mx), e4 = __expf(x4 - mx);
                float s = ((e0 + e1) + (e2 + e3)) + e4;
                s += __shfl_xor_sync(0xffffffffu, s, 1);
                s += __shfl_xor_sync(0xffffffffu, s, 2);
                float inv = __fdividef(1.f, s);
                base[j0]      = e0 * inv * vd[j0];
                base[j0 + 4]  = e1 * inv * vd[j0 + 4];
                base[j0 + 8]  = e2 * inv * vd[j0 + 8];
                base[j0 + 12] = e3 * inv * vd[j0 + 12];
                base[j0 + 16] = e4 * inv * vd[j0 + 16];
            }
            BAR_SYNC(BCONS, 128);

            // ---- P6: m (4 heads/thread, f32x2) -> sM[par] ----
            {
                int nb = u >> 5, dq = (u >> 1) & 15, hg = u & 1;
                const ulonglong2* n2 = reinterpret_cast<const ulonglong2*>(nbase + nb * 1360) + dq;
                const float* a0 = sSC + nb * 224 + (hg * 4 + 0) * 28;
                const float* a1 = sSC + nb * 224 + (hg * 4 + 1) * 28;
                const float* a2 = sSC + nb * 224 + (hg * 4 + 2) * 28;
                const float* a3 = sSC + nb * 224 + (hg * 4 + 3) * 28;
                ull m0a = 0, m0b = 0, m1a = 0, m1b = 0;
                ull m2a = 0, m2b = 0, m3a = 0, m3b = 0;
                #pragma unroll
                for (int jq = 0; jq < 5; ++jq) {
                    float4 w0 = *reinterpret_cast<const float4*>(a0 + jq * 4);
                    float4 w1 = *reinterpret_cast<const float4*>(a1 + jq * 4);
                    float4 w2 = *reinterpret_cast<const float4*>(a2 + jq * 4);
                    float4 w3 = *reinterpret_cast<const float4*>(a3 + jq * 4);
                    #pragma unroll
                    for (int jj = 0; jj < 4; ++jj) {
                        ulonglong2 x = n2[(jq * 4 + jj) * 17];
                        float c0 = jj == 0 ? w0.x : jj == 1 ? w0.y : jj == 2 ? w0.z : w0.w;
                        float c1 = jj == 0 ? w1.x : jj == 1 ? w1.y : jj == 2 ? w1.z : w1.w;
                        float c2 = jj == 0 ? w2.x : jj == 1 ? w2.y : jj == 2 ? w2.z : w2.w;
                        float c3 = jj == 0 ? w3.x : jj == 1 ? w3.y : jj == 2 ? w3.z : w3.w;
                        ull p0 = pk1(c0), p1 = pk1(c1), p2 = pk1(c2), p3 = pk1(c3);
                        fma2(m0a, p0, x.x); fma2(m0b, p0, x.y);
                        fma2(m1a, p1, x.x); fma2(m1b, p1, x.y);
                        fma2(m2a, p2, x.x); fma2(m2b, p2, x.y);
                        fma2(m3a, p3, x.x); fma2(m3b, p3, x.y);
                    }
                }
                float* mb = sMp + nb * 576 + (hg * 4) * 72 + dq * 4;
                ulonglong2* mb2;
                mb2 = reinterpret_cast<ulonglong2*>(mb + 0 * 72); mb2->x = m0a; mb2->y = m0b;
                mb2 = reinterpret_cast<ulonglong2*>(mb + 1 * 72); mb2->x = m1a; mb2->y = m1b;
                mb2 = reinterpret_cast<ulonglong2*>(mb + 2 * 72); mb2->x = m2a; mb2->y = m2b;
                mb2 = reinterpret_cast<ulonglong2*>(mb + 3 * 72); mb2->x = m3a; mb2->y = m3b;
            }
            BAR_SYNC(BCONS, 128);
            BAR_ARRIVE(BEN0 + nb3, 384);

            if (par == 1) {
                // ---- P7: ctx for 8 batches, f32x2 ----
                {
                    int cc = u, h = u >> 4;
                    ull accU[8] = {0,0,0,0,0,0,0,0};
                    #pragma unroll
                    for (int kq = 0; kq < 16; ++kq) {
                        int d = kq * 4;
                        ull w01 = pk2(sWV[(d+0)*128 + cc], sWV[(d+1)*128 + cc]);
                        ull w23 = pk2(sWV[(d+2)*128 + cc], sWV[(d+3)*128 + cc]);
                        #pragma unroll
                        for (int i8 = 0; i8 < 8; ++i8) {
                            ulonglong2 m = *reinterpret_cast<const ulonglong2*>(
                                sM + (i8 >> 2) * 2304 + (i8 & 3) * 576 + h * 72 + d);
                            fma2(accU[i8], w01, m.x);
                            fma2(accU[i8], w23, m.y);
                        }
                    }
                    float bvv = sBV[cc];
                    #pragma unroll
                    for (int i8 = 0; i8 < 8; ++i8) {
                        float2 f = upk(accU[i8]);
                        sCTX[i8 * 128 + cc] = f.x + f.y + bvv;
                    }
                }
                BAR_SYNC(BCONS, 128);

                // ---- P8: out for 8 batches, f32x2 (2-way c split) ----
                {
                    int o = u & 63, cg = u >> 6, c0 = cg * 64;
                    ull accU[8] = {0,0,0,0,0,0,0,0};
                    #pragma unroll
                    for (int kq = 0; kq < 16; ++kq) {
                        int c = c0 + kq * 4;
                        ull w01 = pk2(sWO[(c+0)*64 + o], sWO[(c+1)*64 + o]);
                        ull w23 = pk2(sWO[(c+2)*64 + o], sWO[(c+3)*64 + o]);
                        #pragma unroll
                        for (int i8 = 0; i8 < 8; ++i8) {
                            ulonglong2 x = *reinterpret_cast<const ulonglong2*>(sCTX + i8 * 128 + c);
                            fma2(accU[i8], w01, x.x);
                            fma2(accU[i8], w23, x.y);
                        }
                    }
                    #pragma unroll
                    for (int i8 = 0; i8 < 8; ++i8) {
                        float2 f = upk(accU[i8]);
                        sRED8[cg * 512 + i8 * 64 + o] = f.x + f.y;
                    }
                }
                BAR_SYNC(BCONS, 128);
                #pragma unroll
                for (int p = 0; p < 4; ++p) {
                    int e  = u + p * 128;
                    int i8 = e >> 6, o = e & 63;
                    int bb = (i8 < 4) ? b0_prev : b0;
                    out[(size_t)(bb + (i8 & 3)) * 64 + o] =
                        sRED8[i8 * 64 + o] + sRED8[512 + i8 * 64 + o] + sBO[o];
                }
            } else {
                b0_prev = b0;
            }

            if (++nb3 == 3) nb3 = 0;
        }

        // ---- flush: odd group count leaves sM[0] pending ----
        if (it & 1) {
            {
                int cc = u, h = u >> 4;
                ull accU[4] = {0,0,0,0};
                #pragma unroll
                for (int kq = 0; kq < 16; ++kq) {
                    int d = kq * 4;
                    ull w01 = pk2(sWV[(d+0)*128 + cc], sWV[(d+1)*128 + cc]);
                    ull w23 = pk2(sWV[(d+2)*128 + cc], sWV[(d+3)*128 + cc]);
                    #pragma unroll
                    for (int nb = 0; nb < 4; ++nb) {
                        ulonglong2 m = *reinterpret_cast<const ulonglong2*>(sM + nb * 576 + h * 72 + d);
                        fma2(accU[nb], w01, m.x);
                        fma2(accU[nb], w23, m.y);
                    }
                }
                float bvv = sBV[cc];
                #pragma unroll
                for (int nb = 0; nb < 4; ++nb) {
                    float2 f = upk(accU[nb]);
                    sCTX[nb * 128 + cc] = f.x + f.y + bvv;
                }
            }
            BAR_SYNC(BCONS, 128);
            {
                int o = u & 63, cg = u >> 6, c0 = cg * 64;
                ull accU[4] = {0,0,0,0};
                #pragma unroll
                for (int kq = 0; kq < 16; ++kq) {
                    int c = c0 + kq * 4;
                    ull w01 = pk2(sWO[(c+0)*64 + o], sWO[(c+1)*64 + o]);
                    ull w23 = pk2(sWO[(c+2)*64 + o], sWO[(c+3)*64 + o]);
                    #pragma unroll
                    for (int nb = 0; nb < 4; ++nb) {
                        ulonglong2 x = *reinterpret_cast<const ulonglong2*>(sCTX + nb * 128 + c);
                        fma2(accU[nb], w01, x.x);
                        fma2(accU[nb], w23, x.y);
                    }
                }
                #pragma unroll
                for (int nb = 0; nb < 4; ++nb) {
                    float2 f = upk(accU[nb]);
                    sRED8[cg * 512 + nb * 64 + o] = f.x + f.y;
                }
            }
            BAR_SYNC(BCONS, 128);
            #pragma unroll
            for (int p = 0; p < 2; ++p) {
                int e  = u + p * 128;
                int nb = e >> 6, o = e & 63;
                out[(size_t)(b0_prev + nb) * 64 + o] =
                    sRED8[nb * 64 + o] + sRED8[512 + nb * 64 + o] + sBO[o];
            }
        }
    }
}

extern "C" void kernel_launch(void* const* d_in, const int* in_sizes, int n_in,
                              void* d_out, int out_size)
{
    const float* node_embed = (const float*)d_in[0];
    const int*   start_idx  = (const int*)d_in[1];
    const int*   end_idx    = (const int*)d_in[2];
    /* d_in[3] seg_ids unused (structural) */
    const int*   pad_idx    = (const int*)d_in[4];
    const float* Wq         = (const float*)d_in[5];
    const float* bq         = (const float*)d_in[6];
    const float* Wk         = (const float*)d_in[7];
    /* d_in[8] bk unused (cancels in softmax) */
    const float* Wv         = (const float*)d_in[9];
    const float* bv         = (const float*)d_in[10];
    const float* Wo         = (const float*)d_in[11];
    const float* bo         = (const float*)d_in[12];
    float* out = (float*)d_out;

    int B = out_size / 64;

    cudaFuncSetAttribute(mha_state_encoder_kernel,
                         cudaFuncAttributeMaxDynamicSharedMemorySize, SMEM_BYTES);
    mha_state_encoder_kernel<<<GRID, NT, SMEM_BYTES>>>(
        node_embed, start_idx, end_idx, pad_idx,
        Wq, bq, Wk, Wv, bv, Wo, bo, out, B);
}